// round 14
// baseline (speedup 1.0000x reference)
#include <cuda_runtime.h>
#include <cuda_fp16.h>
#include <math.h>
#include <stdint.h>

#define R_TOT 131072   // BS*N*G rows
#define TOKS  2048     // BS*N tokens

static constexpr size_t OFF_XOUT = 0;
static constexpr size_t OFF_Z    = 16777216;
static constexpr size_t OFF_ZH   = 25165824;
static constexpr size_t OFF_S    = 33554432;
static constexpr size_t OFF_KC   = 33685504;
static constexpr size_t OFF_VP   = 50462720;
static constexpr size_t OFF_G    = 67239936;
static constexpr size_t OFF_QN   = 67371008;
static constexpr size_t OFF_VC   = 84148224;
static constexpr size_t OFF_WN   = 100925440;

// Scratch
__device__ float g_xa[16777216];

// fp16 weights (half2-packed uint32), n-major [n][k]
__device__ uint32_t gw_qkvo[32768];       // [sel][n128][k128/2]
__device__ uint32_t gw_enc [262144];      // [g][n64][k128/2]
__device__ uint32_t gw_pred[131072];      // [g][n64][k64/2]
__device__ uint32_t gw_gain[262144];      // [g][n128][k64/2]
__device__ uint32_t gw_up  [2097152];     // [g][ch4][n128][k128/2]  (8192/chunk)
__device__ uint32_t gw_down[2097152];     // [g][ch4][n128][k128/2]  (8192/chunk)
__device__ uint32_t gw_post[2097152];     // [g][ch4][n128][k128/2]  (8192/chunk)
__device__ float    gw_plast[8192];       // [g][k128]

// ===========================================================================
__device__ __forceinline__ uint32_t pack2(float lo, float hi) {
    uint32_t r;
    asm("cvt.rn.f16x2.f32 %0, %1, %2;" : "=r"(r) : "f"(hi), "f"(lo));
    return r;
}
__device__ __forceinline__ float2 unp2(uint32_t v) {
    __half2 h = *reinterpret_cast<__half2*>(&v);
    return __half22float2(h);
}
__device__ __forceinline__ void mma_h(float* c, uint32_t a0, uint32_t a1,
                                      uint32_t a2, uint32_t a3,
                                      uint32_t b0, uint32_t b1) {
    asm volatile(
        "mma.sync.aligned.m16n8k16.row.col.f32.f16.f16.f32 "
        "{%0,%1,%2,%3}, {%4,%5,%6,%7}, {%8,%9}, {%0,%1,%2,%3};"
        : "+f"(c[0]), "+f"(c[1]), "+f"(c[2]), "+f"(c[3])
        : "r"(a0), "r"(a1), "r"(a2), "r"(a3), "r"(b0), "r"(b1));
}
__device__ __forceinline__ void cp16(void* smem, const void* gmem) {
    uint32_t s = (uint32_t)__cvta_generic_to_shared(smem);
    asm volatile("cp.async.cg.shared.global [%0], [%1], 16;" :: "r"(s), "l"(gmem));
}
__device__ __forceinline__ void cp_commit() {
    asm volatile("cp.async.commit_group;" ::: "memory");
}
template<int N> __device__ __forceinline__ void cp_wait() {
    asm volatile("cp.async.wait_group %0;" :: "n"(N) : "memory");
}
template<int NTHR>
__device__ __forceinline__ void cpy68(uint32_t* dst, const uint32_t* src,
                                      int rows, int tid) {
    for (int i = tid; i < rows * 16; i += NTHR) {
        int r = i >> 4, c = (i & 15) * 4;
        cp16(dst + r * 68 + c, src + r * 64 + c);
    }
}
template<int NTHR>
__device__ __forceinline__ void cpy36(uint32_t* dst, const uint32_t* src,
                                      int rows, int tid) {
    for (int i = tid; i < rows * 8; i += NTHR) {
        int r = i >> 3, c = (i & 7) * 4;
        cp16(dst + r * 36 + c, src + r * 32 + c);
    }
}
template<int LDA, int LDB, int NT>
__device__ __forceinline__ void gemm_h(float acc[NT][4],
        const uint32_t* __restrict__ As, const uint32_t* __restrict__ Bs,
        int mbase, int nbase, int Kw, int q, int t) {
#pragma unroll 2
    for (int kw = 0; kw < Kw; kw += 8) {
        const uint32_t* ap0 = As + (mbase + q) * LDA + kw + t;
        const uint32_t* ap1 = As + (mbase + q + 8) * LDA + kw + t;
        uint32_t a0 = ap0[0], a2 = ap0[4];
        uint32_t a1 = ap1[0], a3 = ap1[4];
#pragma unroll
        for (int nt = 0; nt < NT; nt++) {
            const uint32_t* bp = Bs + (nbase + nt * 8 + q) * LDB + kw + t;
            mma_h(acc[nt], a0, a1, a2, a3, bp[0], bp[4]);
        }
    }
}
__device__ __forceinline__ void zero_acc(float* a, int n) {
#pragma unroll
    for (int i = 0; i < n; i++) a[i] = 0.f;
}

// ===========================================================================
// Weight prep
// ===========================================================================
__global__ void k_tcvt2(const float* __restrict__ src, uint32_t* __restrict__ dst,
                        long sgs, int sld, long gs,
                        int ns, int nchs, int ks, int kchs,
                        int cm, int ldn, int km) {
    __shared__ float tile[32][33];
    int g = blockIdx.z;
    int k0 = blockIdx.x * 32, n0 = blockIdx.y * 32;
    int tr = threadIdx.x >> 5, tc = threadIdx.x & 31;
    const float* s = src + (size_t)g * sgs;
#pragma unroll
    for (int i = 0; i < 4; i++)
        tile[tr + i * 8][tc] = s[(size_t)(k0 + tr + i * 8) * sld + n0 + tc];
    __syncthreads();
    uint32_t* d = dst + (size_t)g * gs;
    int np = threadIdx.x >> 4, kp = threadIdx.x & 15;
#pragma unroll
    for (int ii = 0; ii < 2; ii++) {
        int n = n0 + np + ii * 16, k = k0 + 2 * kp;
        uint32_t v = pack2(tile[2 * kp][np + ii * 16], tile[2 * kp + 1][np + ii * 16]);
        d[(size_t)(n >> ns) * nchs + (size_t)(k >> ks) * kchs
          + (n & cm) * ldn + ((k & km) >> 1)] = v;
    }
}
__global__ void k_tcvt_qkvo2(const float* __restrict__ wq, const float* __restrict__ wk,
                             const float* __restrict__ wv, const float* __restrict__ wo) {
    __shared__ float tile[32][33];
    int sel = blockIdx.z;
    const float* s = (sel == 0) ? wq : (sel == 1) ? wk : (sel == 2) ? wv : wo;
    int k0 = blockIdx.x * 32, n0 = blockIdx.y * 32;
    int tr = threadIdx.x >> 5, tc = threadIdx.x & 31;
#pragma unroll
    for (int i = 0; i < 4; i++)
        tile[tr + i * 8][tc] = s[(size_t)(k0 + tr + i * 8) * 128 + n0 + tc];
    __syncthreads();
    uint32_t* d = gw_qkvo + sel * 8192;
    int np = threadIdx.x >> 4, kp = threadIdx.x & 15;
#pragma unroll
    for (int ii = 0; ii < 2; ii++) {
        int n = n0 + np + ii * 16, k = k0 + 2 * kp;
        d[n * 64 + (k >> 1)] =
            pack2(tile[2 * kp][np + ii * 16], tile[2 * kp + 1][np + ii * 16]);
    }
}
__global__ void k_plast(const float* __restrict__ pw) {
    int i = blockIdx.x * 256 + threadIdx.x;
    if (i < 8192)
        gw_plast[i] = pw[(size_t)i * 513 + 512];
}

// ===========================================================================
// K1: fused LN + QKV + attention + wo.  grid 1024 (128 rows), 512 thr.
// ===========================================================================
__global__ __launch_bounds__(512, 1)
void k_fattn(const float* __restrict__ x,
             const float* __restrict__ latg, const float* __restrict__ latb,
             const float* __restrict__ bq, const float* __restrict__ bk,
             const float* __restrict__ bv, const float* __restrict__ bo) {
    extern __shared__ uint32_t sm[];
    uint32_t* As = sm;                   // 128 x 68 (half)  h, later o
    uint32_t* W0 = As + 8704;
    uint32_t* W1 = W0 + 8704;
    uint32_t* Qh = W1 + 8704;            // 128 x 68 (half)
    float* KVf = (float*)(Qh + 8704);    // 128 x 136 fp32
    float* sc = KVf + 17408;             // 1024
    float* sg = sc + 1024;               // 128
    float* sb = sg + 128;                // 128
    const int tid = threadIdx.x;
    const size_t rowbase = (size_t)blockIdx.x * 128;

    cpy68<512>(W0, gw_qkvo, 128, tid);         cp_commit();  // wq
    cpy68<512>(W1, gw_qkvo + 8192, 128, tid);  cp_commit();  // wk

    if (tid < 128) { sg[tid] = latg[tid]; sb[tid] = latb[tid]; }
    {   // LN -> As fp16
        const int r = tid >> 2, h = tid & 3;
        const float* xr = x + (rowbase + r) * 128 + h * 32;
        float xv[32];
        float s = 0.f, s2 = 0.f;
#pragma unroll
        for (int j = 0; j < 32; j += 4) {
            float4 v = *(const float4*)&xr[j];
            xv[j] = v.x; xv[j + 1] = v.y; xv[j + 2] = v.z; xv[j + 3] = v.w;
            s += v.x + v.y + v.z + v.w;
            s2 += v.x * v.x + v.y * v.y + v.z * v.z + v.w * v.w;
        }
        s  += __shfl_xor_sync(0xffffffffu, s, 1);
        s  += __shfl_xor_sync(0xffffffffu, s, 2);
        s2 += __shfl_xor_sync(0xffffffffu, s2, 1);
        s2 += __shfl_xor_sync(0xffffffffu, s2, 2);
        float mu = s * (1.f / 128.f);
        float rs = rsqrtf(s2 * (1.f / 128.f) - mu * mu + 1e-5f);
        __syncthreads();
        uint32_t* ar = As + r * 68 + h * 16;
#pragma unroll
        for (int j = 0; j < 32; j += 2) {
            int c = h * 32 + j;
            float h0 = (xv[j] - mu) * rs * sg[c] + sb[c];
            float h1 = (xv[j + 1] - mu) * rs * sg[c + 1] + sb[c + 1];
            ar[j >> 1] = pack2(h0, h1);
        }
    }
    __syncthreads();
    cp_wait<1>();
    __syncthreads();

    const int w = tid >> 5, lane = tid & 31, q = lane >> 2, t = lane & 3;
    const int mbase = (w & 7) * 16, nbase = (w >> 3) * 64;

    {   // Q gemm -> Qh fp16
        float acc[8][4];
        zero_acc(&acc[0][0], 32);
        gemm_h<68, 68, 8>(acc, As, W0, mbase, nbase, 64, q, t);
#pragma unroll
        for (int nt = 0; nt < 8; nt++) {
            int rr = mbase + q, cc = nbase + nt * 8 + 2 * t, wi = cc >> 1;
            float b0 = bq[cc], b1 = bq[cc + 1];
            Qh[rr * 68 + wi]       = pack2(acc[nt][0] + b0, acc[nt][1] + b1);
            Qh[(rr + 8) * 68 + wi] = pack2(acc[nt][2] + b0, acc[nt][3] + b1);
        }
    }
    __syncthreads();
    cpy68<512>(W0, gw_qkvo + 16384, 128, tid);     // wv
    cp_commit();
    cp_wait<1>();
    __syncthreads();
    {   // K gemm -> KVf fp32
        float acc[8][4];
        zero_acc(&acc[0][0], 32);
        gemm_h<68, 68, 8>(acc, As, W1, mbase, nbase, 64, q, t);
#pragma unroll
        for (int nt = 0; nt < 8; nt++) {
            int rr = mbase + q, cc = nbase + nt * 8 + 2 * t;
            float b0 = bk[cc], b1 = bk[cc + 1];
            KVf[rr * 136 + cc]           = acc[nt][0] + b0;
            KVf[rr * 136 + cc + 1]       = acc[nt][1] + b1;
            KVf[(rr + 8) * 136 + cc]     = acc[nt][2] + b0;
            KVf[(rr + 8) * 136 + cc + 1] = acc[nt][3] + b1;
        }
    }
    __syncthreads();
    cpy68<512>(W1, gw_qkvo + 24576, 128, tid);     // wo
    cp_commit();
    {   // scores
#pragma unroll
        for (int i = 0; i < 2; i++) {
            int p = tid + 512 * i;
            int rowq = p >> 3;
            int grp = p >> 6, e = p & 7;
            const uint32_t* qp = Qh + rowq * 68;
            const float* kp = KVf + (grp * 8 + e) * 136;
            float s = 0.f;
#pragma unroll 8
            for (int kw = 0; kw < 64; kw += 2) {
                float2 q0 = unp2(qp[kw]);
                float2 q1 = unp2(qp[kw + 1]);
                float4 kv = *(const float4*)&kp[2 * kw];
                s += q0.x * kv.x + q0.y * kv.y + q1.x * kv.z + q1.y * kv.w;
            }
            sc[p] = s * 0.088388347648318447f;
        }
    }
    __syncthreads();
    if (tid < 128) {    // softmax
        float* row = sc + tid * 8;
        float m = row[0];
#pragma unroll
        for (int e = 1; e < 8; e++) m = fmaxf(m, row[e]);
        float ex[8], ssum = 0.f;
#pragma unroll
        for (int e = 0; e < 8; e++) { ex[e] = expf(row[e] - m); ssum += ex[e]; }
        float inv = 1.0f / ssum;
#pragma unroll
        for (int e = 0; e < 8; e++) row[e] = ex[e] * inv;
    }
    cp_wait<1>();
    __syncthreads();
    {   // V gemm -> regs -> overwrite KVf
        float acc[8][4];
        zero_acc(&acc[0][0], 32);
        gemm_h<68, 68, 8>(acc, As, W0, mbase, nbase, 64, q, t);
        __syncthreads();
#pragma unroll
        for (int nt = 0; nt < 8; nt++) {
            int rr = mbase + q, cc = nbase + nt * 8 + 2 * t;
            float b0 = bv[cc], b1 = bv[cc + 1];
            KVf[rr * 136 + cc]           = acc[nt][0] + b0;
            KVf[rr * 136 + cc + 1]       = acc[nt][1] + b1;
            KVf[(rr + 8) * 136 + cc]     = acc[nt][2] + b0;
            KVf[(rr + 8) * 136 + cc + 1] = acc[nt][3] + b1;
        }
    }
    __syncthreads();
    {   // o = attn @ V -> As fp16
        int rr = tid >> 2, d0 = (tid & 3) * 32;
        const float* vb = KVf + (rr & ~7) * 136;
        float a[8];
#pragma unroll
        for (int e = 0; e < 8; e++) a[e] = sc[rr * 8 + e];
        uint32_t* ar = As + rr * 68 + (d0 >> 1);
#pragma unroll
        for (int j = 0; j < 32; j += 4) {
            float4 o = make_float4(0.f, 0.f, 0.f, 0.f);
#pragma unroll
            for (int e = 0; e < 8; e++) {
                float4 v = *(const float4*)&vb[e * 136 + d0 + j];
                o.x += a[e] * v.x; o.y += a[e] * v.y;
                o.z += a[e] * v.z; o.w += a[e] * v.w;
            }
            ar[(j >> 1)]     = pack2(o.x, o.y);
            ar[(j >> 1) + 1] = pack2(o.z, o.w);
        }
    }
    cp_wait<0>();
    __syncthreads();
    {   // wo gemm + residual -> g_xa
        float acc[8][4];
        zero_acc(&acc[0][0], 32);
        gemm_h<68, 68, 8>(acc, As, W1, mbase, nbase, 64, q, t);
#pragma unroll
        for (int nt = 0; nt < 8; nt++) {
            int rr = mbase + q, cc = nbase + nt * 8 + 2 * t;
            float b0 = bo[cc], b1 = bo[cc + 1];
            size_t o0 = (rowbase + rr) * 128 + cc;
            size_t o1 = (rowbase + rr + 8) * 128 + cc;
            float2 x0 = *(const float2*)&x[o0];
            float2 x1 = *(const float2*)&x[o1];
            *(float2*)&g_xa[o0] = make_float2(x0.x + acc[nt][0] + b0,
                                              x0.y + acc[nt][1] + b1);
            *(float2*)&g_xa[o1] = make_float2(x1.x + acc[nt][2] + b0,
                                              x1.y + acc[nt][3] + b1);
        }
    }
}

// ===========================================================================
// K2: mega per-group kernel, 64-token tiles, 256 thr, 2 CTAs/SM.
// grid (32, 64). words: As 4352 | Zs 2304 | Ds 2304 | B0 8704 | B1 8704 | 256
// ===========================================================================
__global__ __launch_bounds__(256, 2)
void k_mega(const float* __restrict__ zhp,
            const float* __restrict__ lng, const float* __restrict__ lnb,
            const float* __restrict__ encb, const float* __restrict__ predb,
            const float* __restrict__ gainb, const float* __restrict__ upb,
            const float* __restrict__ dwb, const float* __restrict__ pb,
            float* out) {
    extern __shared__ uint32_t sm[];
    uint32_t* As = sm;                  // 64 x 68 (half)
    uint32_t* Zs = As + 4352;           // 64 x 36 (half)
    uint32_t* Ds = Zs + 2304;           // 64 x 36 (half)
    uint32_t* B0 = Ds + 2304;           // 8704
    uint32_t* B1 = B0 + 8704;           // 8704
    float* smu = (float*)(B1 + 8704);   // 64
    float* srs = smu + 64;              // 64
    float* pr  = srs + 64;              // 128
    const int tid = threadIdx.x;
    const int g = blockIdx.y, p0 = blockIdx.x * 64;

    cpy68<256>(B0, gw_enc + (size_t)g * 4096, 64, tid);   cp_commit();
    cpy36<256>(B1, gw_pred + (size_t)g * 2048, 64, tid);  cp_commit();

    {   // As = fp16(x_attn), stats: 64 rows x 4 thr, 32 cols each
        const int r = tid >> 2, h = tid & 3;
        const float* xr = g_xa + ((size_t)(p0 + r) * 64 + g) * 128 + h * 32;
        float xv[32];
        float s = 0.f, s2 = 0.f;
#pragma unroll
        for (int j = 0; j < 32; j += 4) {
            float4 v = *(const float4*)&xr[j];
            xv[j] = v.x; xv[j + 1] = v.y; xv[j + 2] = v.z; xv[j + 3] = v.w;
            s += v.x + v.y + v.z + v.w;
            s2 += v.x * v.x + v.y * v.y + v.z * v.z + v.w * v.w;
        }
        uint32_t* ar = As + r * 68 + h * 16;
#pragma unroll
        for (int j = 0; j < 32; j += 2)
            ar[j >> 1] = pack2(xv[j], xv[j + 1]);
        s  += __shfl_xor_sync(0xffffffffu, s, 1);
        s  += __shfl_xor_sync(0xffffffffu, s, 2);
        s2 += __shfl_xor_sync(0xffffffffu, s2, 1);
        s2 += __shfl_xor_sync(0xffffffffu, s2, 2);
        float mu = s * (1.f / 128.f);
        if (h == 0) {
            smu[r] = mu;
            srs[r] = rsqrtf(s2 * (1.f / 128.f) - mu * mu + 1e-5f);
        }
    }
    cp_wait<1>();     // enc ready
    __syncthreads();

    const int w = tid >> 5, lane = tid & 31, q = lane >> 2, t = lane & 3;
    const int mbase = (w & 3) * 16, wn = w >> 2;

    {   // enc GEMM (16 x 32 per warp, Kw=64)
        float acc[4][4];
        zero_acc(&acc[0][0], 16);
        gemm_h<68, 68, 4>(acc, As, B0, mbase, wn * 32, 64, q, t);
        float sl = 0.f, sh = 0.f;
#pragma unroll
        for (int nt = 0; nt < 4; nt++) {
            int cc = wn * 32 + nt * 8 + 2 * t;
            int rlo = mbase + q, rhi = rlo + 8;
            float z0 = acc[nt][0] + encb[g * 64 + cc];
            float z1 = acc[nt][1] + encb[g * 64 + cc + 1];
            float z2 = acc[nt][2] + encb[g * 64 + cc];
            float z3 = acc[nt][3] + encb[g * 64 + cc + 1];
            size_t qlo = (size_t)(p0 + rlo) * 64 + g;
            size_t qhi = (size_t)(p0 + rhi) * 64 + g;
            *(float2*)&out[OFF_Z + qlo * 64 + cc] = make_float2(z0, z1);
            *(float2*)&out[OFF_Z + qhi * 64 + cc] = make_float2(z2, z3);
            float2 plo = *(const float2*)&zhp[qlo * 64 + cc];
            float2 phi = *(const float2*)&zhp[qhi * 64 + cc];
            float d0 = z0 - plo.x, d1 = z1 - plo.y;
            float d2 = z2 - phi.x, d3 = z3 - phi.y;
            int wi = cc >> 1;
            Zs[rlo * 36 + wi] = pack2(z0, z1);
            Zs[rhi * 36 + wi] = pack2(z2, z3);
            Ds[rlo * 36 + wi] = pack2(d0, d1);
            Ds[rhi * 36 + wi] = pack2(d2, d3);
            sl += d0 * d0 + d1 * d1;
            sh += d2 * d2 + d3 * d3;
        }
        sl += __shfl_xor_sync(0xffffffffu, sl, 1);
        sl += __shfl_xor_sync(0xffffffffu, sl, 2);
        sh += __shfl_xor_sync(0xffffffffu, sh, 1);
        sh += __shfl_xor_sync(0xffffffffu, sh, 2);
        if (t == 0) {
            pr[wn * 64 + mbase + q] = sl;
            pr[wn * 64 + mbase + q + 8] = sh;
        }
    }
    __syncthreads();
    if (tid < 64) {   // surprise + gate
        float sp = sqrtf(pr[tid] + pr[64 + tid]);
        size_t qq = (size_t)(p0 + tid) * 64 + g;
        out[OFF_S + qq] = sp;
        out[OFF_G + qq] = fminf(sp, 1.0f);
    }
    cpy68<256>(B0, gw_up + (size_t)g * 32768, 128, tid);     cp_commit();   // up0
    cp_wait<1>();                                            // pred ready
    __syncthreads();
    {   // pred GEMM (Kw=32)
        float acc[4][4];
        zero_acc(&acc[0][0], 16);
        gemm_h<36, 36, 4>(acc, Zs, B1, mbase, wn * 32, 32, q, t);
#pragma unroll
        for (int nt = 0; nt < 4; nt++) {
            int cc = wn * 32 + nt * 8 + 2 * t;
            size_t qlo = (size_t)(p0 + mbase + q) * 64 + g;
            size_t qhi = (size_t)(p0 + mbase + q + 8) * 64 + g;
            float b0 = predb[g * 64 + cc], b1 = predb[g * 64 + cc + 1];
            *(float2*)&out[OFF_ZH + qlo * 64 + cc] =
                make_float2(acc[nt][0] + b0, acc[nt][1] + b1);
            *(float2*)&out[OFF_ZH + qhi * 64 + cc] =
                make_float2(acc[nt][2] + b0, acc[nt][3] + b1);
        }
    }
    __syncthreads();
    cpy36<256>(B1, gw_gain + (size_t)g * 4096, 128, tid);    cp_commit();   // gain
    cp_wait<0>();
    __syncthreads();
    {   // gain GEMM (16x64 per warp, Kw=32) + GLN epilogue -> As := fp16(hh)
        float acc[8][4];
        zero_acc(&acc[0][0], 32);
        gemm_h<36, 36, 8>(acc, Ds, B1, mbase, wn * 64, 32, q, t);
        int rlo = mbase + q, rhi = rlo + 8;
        float mlo = smu[rlo], rslo = srs[rlo];
        float mhi = smu[rhi], rshi = srs[rhi];
#pragma unroll
        for (int nt = 0; nt < 8; nt++) {
            int cc = wn * 64 + nt * 8 + 2 * t, wi = cc >> 1;
            float lg0 = lng[(size_t)g * 128 + cc], lb0 = lnb[(size_t)g * 128 + cc];
            float lg1 = lng[(size_t)g * 128 + cc + 1], lb1 = lnb[(size_t)g * 128 + cc + 1];
            float gb0 = gainb[(size_t)g * 128 + cc], gb1 = gainb[(size_t)g * 128 + cc + 1];
            float2 xlo = unp2(As[rlo * 68 + wi]);
            float2 xhi = unp2(As[rhi * 68 + wi]);
            float h00 = ((xlo.x - mlo) * rslo * lg0 + lb0)
                        * (1.0f + 0.1f * tanhf(acc[nt][0] + gb0));
            float h01 = ((xlo.y - mlo) * rslo * lg1 + lb1)
                        * (1.0f + 0.1f * tanhf(acc[nt][1] + gb1));
            float h10 = ((xhi.x - mhi) * rshi * lg0 + lb0)
                        * (1.0f + 0.1f * tanhf(acc[nt][2] + gb0));
            float h11 = ((xhi.y - mhi) * rshi * lg1 + lb1)
                        * (1.0f + 0.1f * tanhf(acc[nt][3] + gb1));
            As[rlo * 68 + wi] = pack2(h00, h01);
            As[rhi * 68 + wi] = pack2(h10, h11);
        }
    }
    __syncthreads();
    cpy68<256>(B1, gw_down + (size_t)g * 32768, 128, tid);   cp_commit();   // down0

    uint32_t* Us = Zs;   // 64 x 68 overlays Zs+Ds (4352 <= 4608)
    float oacc[8][4];
    zero_acc(&oacc[0][0], 32);
    for (int ch = 0; ch < 4; ch++) {
        float uacc[8][4];
        zero_acc(&uacc[0][0], 32);
        gemm_h<68, 68, 8>(uacc, As, B0, mbase, wn * 64, 64, q, t);
#pragma unroll
        for (int nt = 0; nt < 8; nt++) {
            int cc = wn * 64 + nt * 8 + 2 * t, wi = cc >> 1;
            int rlo = mbase + q, rhi = rlo + 8;
            float b0 = upb[(size_t)g * 512 + ch * 128 + cc];
            float b1 = upb[(size_t)g * 512 + ch * 128 + cc + 1];
            float u00 = uacc[nt][0] + b0, u01 = uacc[nt][1] + b1;
            float u10 = uacc[nt][2] + b0, u11 = uacc[nt][3] + b1;
            u00 = 0.5f * u00 * (1.0f + erff(u00 * 0.70710678118654752f));
            u01 = 0.5f * u01 * (1.0f + erff(u01 * 0.70710678118654752f));
            u10 = 0.5f * u10 * (1.0f + erff(u10 * 0.70710678118654752f));
            u11 = 0.5f * u11 * (1.0f + erff(u11 * 0.70710678118654752f));
            Us[rlo * 68 + wi] = pack2(u00, u01);
            Us[rhi * 68 + wi] = pack2(u10, u11);
        }
        __syncthreads();
        if (ch < 3) {
            cpy68<256>(B0, gw_up + (size_t)g * 32768 + (ch + 1) * 8192, 128, tid);
            cp_commit();
            cp_wait<1>();
        } else {
            cp_wait<0>();
        }
        __syncthreads();
        gemm_h<68, 68, 8>(oacc, Us, B1, mbase, wn * 64, 64, q, t);
        if (ch < 3) {
            __syncthreads();
            cpy68<256>(B1, gw_down + (size_t)g * 32768 + (ch + 1) * 8192, 128, tid);
            cp_commit();
            cp_wait<1>();
            __syncthreads();
        }
    }
    __syncthreads();
    {   // MLP epilogue -> gmem x_out AND As := fp16(x_out)
#pragma unroll
        for (int nt = 0; nt < 8; nt++) {
            int cc = wn * 64 + nt * 8 + 2 * t, wi = cc >> 1;
            int rlo = mbase + q, rhi = rlo + 8;
            float b0 = dwb[(size_t)g * 128 + cc], b1 = dwb[(size_t)g * 128 + cc + 1];
            size_t o0 = ((size_t)(p0 + rlo) * 64 + g) * 128 + cc;
            size_t o1 = ((size_t)(p0 + rhi) * 64 + g) * 128 + cc;
            float2 x0 = *(const float2*)&g_xa[o0];
            float2 x1 = *(const float2*)&g_xa[o1];
            float v00 = x0.x + oacc[nt][0] + b0, v01 = x0.y + oacc[nt][1] + b1;
            float v10 = x1.x + oacc[nt][2] + b0, v11 = x1.y + oacc[nt][3] + b1;
            *(float2*)&out[OFF_XOUT + o0] = make_float2(v00, v01);
            *(float2*)&out[OFF_XOUT + o1] = make_float2(v10, v11);
            As[rlo * 68 + wi] = pack2(v00, v01);
            As[rhi * 68 + wi] = pack2(v10, v11);
        }
    }
    __syncthreads();
    cpy68<256>(B0, gw_post + (size_t)g * 32768, 128, tid);         cp_commit();
    cpy68<256>(B1, gw_post + (size_t)g * 32768 + 8192, 128, tid);  cp_commit();

    if (tid < 64) {   // w_nov
        const float* wl = gw_plast + g * 128;
        float s = 0.f;
        for (int kw = 0; kw < 64; kw++) {
            float2 xv = unp2(As[tid * 68 + kw]);
            s += xv.x * wl[2 * kw] + xv.y * wl[2 * kw + 1];
        }
        s += pb[(size_t)g * 513 + 512];
        out[OFF_WN + (size_t)(p0 + tid) * 64 + g] = 1.0f / (1.0f + expf(-s));
    }

    for (int ch = 0; ch < 4; ch++) {
        if (ch < 3) cp_wait<1>(); else cp_wait<0>();
        __syncthreads();
        uint32_t* Bs = (ch & 1) ? B1 : B0;
        float acc[8][4];
        zero_acc(&acc[0][0], 32);
        gemm_h<68, 68, 8>(acc, As, Bs, mbase, wn * 64, 64, q, t);
#pragma unroll
        for (int nt = 0; nt < 8; nt++) {
            int cc = wn * 64 + nt * 8 + 2 * t;
            float b0 = pb[(size_t)g * 513 + ch * 128 + cc];
            float b1 = pb[(size_t)g * 513 + ch * 128 + cc + 1];
            acc[nt][0] += b0; acc[nt][1] += b1;
            acc[nt][2] += b0; acc[nt][3] += b1;
        }
        if (ch == 1 || ch == 3) {
            size_t off = (ch == 1) ? OFF_VP : OFF_VC;
#pragma unroll
            for (int nt = 0; nt < 8; nt++) {
                int rr = mbase + q, cc = wn * 64 + nt * 8 + 2 * t;
                size_t o0 = off + ((size_t)(p0 + rr) * 64 + g) * 128 + cc;
                size_t o1 = off + ((size_t)(p0 + rr + 8) * 64 + g) * 128 + cc;
                *(float2*)&out[o0] = make_float2(acc[nt][0], acc[nt][1]);
                *(float2*)&out[o1] = make_float2(acc[nt][2], acc[nt][3]);
            }
        } else {
            float sl = 0.f, sh = 0.f;
#pragma unroll
            for (int nt = 0; nt < 8; nt++) {
                sl += acc[nt][0] * acc[nt][0] + acc[nt][1] * acc[nt][1];
                sh += acc[nt][2] * acc[nt][2] + acc[nt][3] * acc[nt][3];
            }
            sl += __shfl_xor_sync(0xffffffffu, sl, 1);
            sl += __shfl_xor_sync(0xffffffffu, sl, 2);
            sh += __shfl_xor_sync(0xffffffffu, sh, 1);
            sh += __shfl_xor_sync(0xffffffffu, sh, 2);
            if (t == 0) {
                pr[wn * 64 + mbase + q] = sl;
                pr[wn * 64 + mbase + q + 8] = sh;
            }
            __syncthreads();
            size_t off = (ch == 0) ? OFF_KC : OFF_QN;
#pragma unroll
            for (int nt = 0; nt < 8; nt++) {
                int rr = mbase + q, cc = wn * 64 + nt * 8 + 2 * t;
                float i0 = 1.0f / fmaxf(sqrtf(pr[rr] + pr[64 + rr]), 1e-6f);
                float i1 = 1.0f / fmaxf(sqrtf(pr[rr + 8] + pr[64 + rr + 8]), 1e-6f);
                size_t o0 = off + ((size_t)(p0 + rr) * 64 + g) * 128 + cc;
                size_t o1 = off + ((size_t)(p0 + rr + 8) * 64 + g) * 128 + cc;
                *(float2*)&out[o0] = make_float2(acc[nt][0] * i0, acc[nt][1] * i0);
                *(float2*)&out[o1] = make_float2(acc[nt][2] * i1, acc[nt][3] * i1);
            }
        }
        if (ch < 2) {
            __syncthreads();
            cpy68<256>((ch & 1) ? B1 : B0,
                       gw_post + (size_t)g * 32768 + (ch + 2) * 8192, 128, tid);
            cp_commit();
        }
    }
}

// ===========================================================================
extern "C" void kernel_launch(void* const* d_in, const int* in_sizes, int n_in,
                              void* d_out, int out_size) {
    const float* x_col  = (const float*)d_in[0];
    const float* zhp    = (const float*)d_in[1];
    const float* ln_g   = (const float*)d_in[2];
    const float* ln_b   = (const float*)d_in[3];
    const float* up_w   = (const float*)d_in[4];
    const float* up_b   = (const float*)d_in[5];
    const float* down_w = (const float*)d_in[6];
    const float* down_b = (const float*)d_in[7];
    const float* lat_g  = (const float*)d_in[8];
    const float* lat_b  = (const float*)d_in[9];
    const float* wq     = (const float*)d_in[10];
    const float* bq     = (const float*)d_in[11];
    const float* wk     = (const float*)d_in[12];
    const float* bk     = (const float*)d_in[13];
    const float* wv     = (const float*)d_in[14];
    const float* bv     = (const float*)d_in[15];
    const float* wo     = (const float*)d_in[16];
    const float* bo     = (const float*)d_in[17];
    const float* post_w = (const float*)d_in[18];
    const float* post_b = (const float*)d_in[19];
    const float* enc_w  = (const float*)d_in[20];
    const float* enc_b  = (const float*)d_in[21];
    const float* pred_w = (const float*)d_in[22];
    const float* pred_b = (const float*)d_in[23];
    const float* gain_w = (const float*)d_in[24];
    const float* gain_b = (const float*)d_in[25];
    float* out = (float*)d_out;

    const int SM_FA   = 53504 * 4;   // 214016
    const int SM_MEGA = 26624 * 4;   // 106496  (2 CTAs/SM)

    cudaFuncSetAttribute(k_fattn, cudaFuncAttributeMaxDynamicSharedMemorySize, SM_FA);
    cudaFuncSetAttribute(k_mega,  cudaFuncAttributeMaxDynamicSharedMemorySize, SM_MEGA);

    uint32_t* d_enc;  cudaGetSymbolAddress((void**)&d_enc,  gw_enc);
    uint32_t* d_pred; cudaGetSymbolAddress((void**)&d_pred, gw_pred);
    uint32_t* d_gain; cudaGetSymbolAddress((void**)&d_gain, gw_gain);
    uint32_t* d_up;   cudaGetSymbolAddress((void**)&d_up,   gw_up);
    uint32_t* d_down; cudaGetSymbolAddress((void**)&d_down, gw_down);
    uint32_t* d_post; cudaGetSymbolAddress((void**)&d_post, gw_post);

    k_tcvt_qkvo2<<<dim3(4, 4, 4), 256>>>(wq, wk, wv, wo);
    k_tcvt2<<<dim3(4, 2, 64), 256>>>(enc_w, d_enc, 8192, 64, 4096,
                                     6, 0, 7, 0, 63, 64, 127);
    k_tcvt2<<<dim3(2, 2, 64), 256>>>(pred_w, d_pred, 4096, 64, 2048,
                                     6, 0, 6, 0, 63, 32, 63);
    k_tcvt2<<<dim3(2, 4, 64), 256>>>(gain_w, d_gain, 8192, 128, 4096,
                                     7, 0, 6, 0, 127, 32, 63);
    k_tcvt2<<<dim3(4, 16, 64), 256>>>(up_w, d_up, 65536, 512, 32768,
                                      7, 8192, 7, 0, 127, 64, 127);
    k_tcvt2<<<dim3(16, 4, 64), 256>>>(down_w, d_down, 65536, 128, 32768,
                                      7, 0, 7, 8192, 127, 64, 127);
    k_tcvt2<<<dim3(4, 16, 64), 256>>>(post_w, d_post, 65664, 513, 32768,
                                      7, 8192, 7, 0, 127, 64, 127);
    k_plast<<<32, 256>>>(post_w);

    k_fattn<<<R_TOT / 128, 512, SM_FA>>>(x_col, lat_g, lat_b, bq, bk, bv, bo);
    k_mega<<<dim3(TOKS / 64, 64), 256, SM_MEGA>>>(zhp, ln_g, ln_b,
                                                  enc_b, pred_b, gain_b,
                                                  up_b, down_b, post_b, out);
}

// round 15
// speedup vs baseline: 1.0023x; 1.0023x over previous
#include <cuda_runtime.h>
#include <cuda_fp16.h>
#include <math.h>
#include <stdint.h>

#define R_TOT 131072   // BS*N*G rows
#define TOKS  2048     // BS*N tokens

static constexpr size_t OFF_XOUT = 0;
static constexpr size_t OFF_Z    = 16777216;
static constexpr size_t OFF_ZH   = 25165824;
static constexpr size_t OFF_S    = 33554432;
static constexpr size_t OFF_KC   = 33685504;
static constexpr size_t OFF_VP   = 50462720;
static constexpr size_t OFF_G    = 67239936;
static constexpr size_t OFF_QN   = 67371008;
static constexpr size_t OFF_VC   = 84148224;
static constexpr size_t OFF_WN   = 100925440;

// Scratch
__device__ float g_xa[16777216];

// fp16 weights (half2-packed uint32), n-major [n][k]
__device__ uint32_t gw_qkvo[32768];       // [sel][n128][k128/2]
__device__ uint32_t gw_enc [262144];      // [g][n64][k128/2]
__device__ uint32_t gw_pred[131072];      // [g][n64][k64/2]
__device__ uint32_t gw_gain[262144];      // [g][n128][k64/2]
__device__ uint32_t gw_up  [2097152];     // [g][ch4][n128][k128/2]  (8192/chunk)
__device__ uint32_t gw_down[2097152];     // [g][ch4][n128][k128/2]  (8192/chunk)
__device__ uint32_t gw_post[2097152];     // [g][ch4][n128][k128/2]  (8192/chunk)
__device__ float    gw_plast[8192];       // [g][k128]

// ===========================================================================
__device__ __forceinline__ uint32_t pack2(float lo, float hi) {
    uint32_t r;
    asm("cvt.rn.f16x2.f32 %0, %1, %2;" : "=r"(r) : "f"(hi), "f"(lo));
    return r;
}
__device__ __forceinline__ float2 unp2(uint32_t v) {
    __half2 h = *reinterpret_cast<__half2*>(&v);
    return __half22float2(h);
}
__device__ __forceinline__ void mma_h(float* c, uint32_t a0, uint32_t a1,
                                      uint32_t a2, uint32_t a3,
                                      uint32_t b0, uint32_t b1) {
    asm volatile(
        "mma.sync.aligned.m16n8k16.row.col.f32.f16.f16.f32 "
        "{%0,%1,%2,%3}, {%4,%5,%6,%7}, {%8,%9}, {%0,%1,%2,%3};"
        : "+f"(c[0]), "+f"(c[1]), "+f"(c[2]), "+f"(c[3])
        : "r"(a0), "r"(a1), "r"(a2), "r"(a3), "r"(b0), "r"(b1));
}
__device__ __forceinline__ void cp16(void* smem, const void* gmem) {
    uint32_t s = (uint32_t)__cvta_generic_to_shared(smem);
    asm volatile("cp.async.cg.shared.global [%0], [%1], 16;" :: "r"(s), "l"(gmem));
}
__device__ __forceinline__ void cp_commit() {
    asm volatile("cp.async.commit_group;" ::: "memory");
}
template<int N> __device__ __forceinline__ void cp_wait() {
    asm volatile("cp.async.wait_group %0;" :: "n"(N) : "memory");
}
template<int NTHR>
__device__ __forceinline__ void cpy68(uint32_t* dst, const uint32_t* src,
                                      int rows, int tid) {
    for (int i = tid; i < rows * 16; i += NTHR) {
        int r = i >> 4, c = (i & 15) * 4;
        cp16(dst + r * 68 + c, src + r * 64 + c);
    }
}
template<int NTHR>
__device__ __forceinline__ void cpy36(uint32_t* dst, const uint32_t* src,
                                      int rows, int tid) {
    for (int i = tid; i < rows * 8; i += NTHR) {
        int r = i >> 3, c = (i & 7) * 4;
        cp16(dst + r * 36 + c, src + r * 32 + c);
    }
}
template<int LDA, int LDB, int NT>
__device__ __forceinline__ void gemm_h(float acc[NT][4],
        const uint32_t* __restrict__ As, const uint32_t* __restrict__ Bs,
        int mbase, int nbase, int Kw, int q, int t) {
#pragma unroll 2
    for (int kw = 0; kw < Kw; kw += 8) {
        const uint32_t* ap0 = As + (mbase + q) * LDA + kw + t;
        const uint32_t* ap1 = As + (mbase + q + 8) * LDA + kw + t;
        uint32_t a0 = ap0[0], a2 = ap0[4];
        uint32_t a1 = ap1[0], a3 = ap1[4];
#pragma unroll
        for (int nt = 0; nt < NT; nt++) {
            const uint32_t* bp = Bs + (nbase + nt * 8 + q) * LDB + kw + t;
            mma_h(acc[nt], a0, a1, a2, a3, bp[0], bp[4]);
        }
    }
}
__device__ __forceinline__ void zero_acc(float* a, int n) {
#pragma unroll
    for (int i = 0; i < n; i++) a[i] = 0.f;
}

// ===========================================================================
// Weight prep
// ===========================================================================
__global__ void k_tcvt2(const float* __restrict__ src, uint32_t* __restrict__ dst,
                        long sgs, int sld, long gs,
                        int ns, int nchs, int ks, int kchs,
                        int cm, int ldn, int km) {
    __shared__ float tile[32][33];
    int g = blockIdx.z;
    int k0 = blockIdx.x * 32, n0 = blockIdx.y * 32;
    int tr = threadIdx.x >> 5, tc = threadIdx.x & 31;
    const float* s = src + (size_t)g * sgs;
#pragma unroll
    for (int i = 0; i < 4; i++)
        tile[tr + i * 8][tc] = s[(size_t)(k0 + tr + i * 8) * sld + n0 + tc];
    __syncthreads();
    uint32_t* d = dst + (size_t)g * gs;
    int np = threadIdx.x >> 4, kp = threadIdx.x & 15;
#pragma unroll
    for (int ii = 0; ii < 2; ii++) {
        int n = n0 + np + ii * 16, k = k0 + 2 * kp;
        uint32_t v = pack2(tile[2 * kp][np + ii * 16], tile[2 * kp + 1][np + ii * 16]);
        d[(size_t)(n >> ns) * nchs + (size_t)(k >> ks) * kchs
          + (n & cm) * ldn + ((k & km) >> 1)] = v;
    }
}
__global__ void k_tcvt_qkvo2(const float* __restrict__ wq, const float* __restrict__ wk,
                             const float* __restrict__ wv, const float* __restrict__ wo) {
    __shared__ float tile[32][33];
    int sel = blockIdx.z;
    const float* s = (sel == 0) ? wq : (sel == 1) ? wk : (sel == 2) ? wv : wo;
    int k0 = blockIdx.x * 32, n0 = blockIdx.y * 32;
    int tr = threadIdx.x >> 5, tc = threadIdx.x & 31;
#pragma unroll
    for (int i = 0; i < 4; i++)
        tile[tr + i * 8][tc] = s[(size_t)(k0 + tr + i * 8) * 128 + n0 + tc];
    __syncthreads();
    uint32_t* d = gw_qkvo + sel * 8192;
    int np = threadIdx.x >> 4, kp = threadIdx.x & 15;
#pragma unroll
    for (int ii = 0; ii < 2; ii++) {
        int n = n0 + np + ii * 16, k = k0 + 2 * kp;
        d[n * 64 + (k >> 1)] =
            pack2(tile[2 * kp][np + ii * 16], tile[2 * kp + 1][np + ii * 16]);
    }
}
__global__ void k_plast(const float* __restrict__ pw) {
    int i = blockIdx.x * 256 + threadIdx.x;
    if (i < 8192)
        gw_plast[i] = pw[(size_t)i * 513 + 512];
}

// ===========================================================================
// K1: fused LN + QKV + attention + wo.  64-row tiles, 256 thr, 2 CTAs/SM.
// grid 2048. words: As 4352 | W 8704 | Qh 4352 | KVf 8704 | sc 512 | sg/sb 256
// total 26880 words = 107.5 KB
// ===========================================================================
__global__ __launch_bounds__(256, 2)
void k_fattn(const float* __restrict__ x,
             const float* __restrict__ latg, const float* __restrict__ latb,
             const float* __restrict__ bq, const float* __restrict__ bk,
             const float* __restrict__ bv, const float* __restrict__ bo) {
    extern __shared__ uint32_t sm[];
    uint32_t* As = sm;                   // 64 x 68 (half)  h, later o
    uint32_t* W  = As + 4352;            // 128 x 68 (half) weight (single buffer)
    uint32_t* Qh = W + 8704;             // 64 x 68 (half)  Q
    float* KVf = (float*)(Qh + 4352);    // 64 x 136 fp32   K then V
    float* sc = KVf + 8704;              // 512
    float* sg = sc + 512;                // 128
    float* sb = sg + 128;                // 128
    const int tid = threadIdx.x;
    const size_t rowbase = (size_t)blockIdx.x * 64;

    cpy68<256>(W, gw_qkvo, 128, tid);  cp_commit();  // wq

    if (tid < 128) { sg[tid] = latg[tid]; sb[tid] = latb[tid]; }
    {   // LN: 64 rows x 4 thr, 32 cols each -> As fp16
        const int r = tid >> 2, h = tid & 3;
        const float* xr = x + (rowbase + r) * 128 + h * 32;
        float xv[32];
        float s = 0.f, s2 = 0.f;
#pragma unroll
        for (int j = 0; j < 32; j += 4) {
            float4 v = *(const float4*)&xr[j];
            xv[j] = v.x; xv[j + 1] = v.y; xv[j + 2] = v.z; xv[j + 3] = v.w;
            s += v.x + v.y + v.z + v.w;
            s2 += v.x * v.x + v.y * v.y + v.z * v.z + v.w * v.w;
        }
        s  += __shfl_xor_sync(0xffffffffu, s, 1);
        s  += __shfl_xor_sync(0xffffffffu, s, 2);
        s2 += __shfl_xor_sync(0xffffffffu, s2, 1);
        s2 += __shfl_xor_sync(0xffffffffu, s2, 2);
        float mu = s * (1.f / 128.f);
        float rs = rsqrtf(s2 * (1.f / 128.f) - mu * mu + 1e-5f);
        __syncthreads();   // sg/sb visible
        uint32_t* ar = As + r * 68 + h * 16;
#pragma unroll
        for (int j = 0; j < 32; j += 2) {
            int c = h * 32 + j;
            float h0 = (xv[j] - mu) * rs * sg[c] + sb[c];
            float h1 = (xv[j + 1] - mu) * rs * sg[c + 1] + sb[c + 1];
            ar[j >> 1] = pack2(h0, h1);
        }
    }
    __syncthreads();       // As final
    cp_wait<0>();          // wq arrived
    __syncthreads();

    const int w = tid >> 5, lane = tid & 31, q = lane >> 2, t = lane & 3;
    const int mbase = (w & 3) * 16, nbase = (w >> 2) * 64;

    {   // Q gemm -> Qh fp16
        float acc[8][4];
        zero_acc(&acc[0][0], 32);
        gemm_h<68, 68, 8>(acc, As, W, mbase, nbase, 64, q, t);
#pragma unroll
        for (int nt = 0; nt < 8; nt++) {
            int rr = mbase + q, cc = nbase + nt * 8 + 2 * t, wi = cc >> 1;
            float b0 = bq[cc], b1 = bq[cc + 1];
            Qh[rr * 68 + wi]       = pack2(acc[nt][0] + b0, acc[nt][1] + b1);
            Qh[(rr + 8) * 68 + wi] = pack2(acc[nt][2] + b0, acc[nt][3] + b1);
        }
    }
    __syncthreads();                          // W(wq) reads done
    cpy68<256>(W, gw_qkvo + 8192, 128, tid);  // wk
    cp_commit();
    cp_wait<0>();
    __syncthreads();
    {   // K gemm -> KVf fp32
        float acc[8][4];
        zero_acc(&acc[0][0], 32);
        gemm_h<68, 68, 8>(acc, As, W, mbase, nbase, 64, q, t);
#pragma unroll
        for (int nt = 0; nt < 8; nt++) {
            int rr = mbase + q, cc = nbase + nt * 8 + 2 * t;
            float b0 = bk[cc], b1 = bk[cc + 1];
            KVf[rr * 136 + cc]           = acc[nt][0] + b0;
            KVf[rr * 136 + cc + 1]       = acc[nt][1] + b1;
            KVf[(rr + 8) * 136 + cc]     = acc[nt][2] + b0;
            KVf[(rr + 8) * 136 + cc + 1] = acc[nt][3] + b1;
        }
    }
    __syncthreads();                          // W(wk) reads done; K final
    cpy68<256>(W, gw_qkvo + 16384, 128, tid); // wv (overlaps scores)
    cp_commit();
    {   // scores: 512 (grp,c,e) pairs, two per thread
#pragma unroll
        for (int i = 0; i < 2; i++) {
            int p = tid + 256 * i;
            int rowq = p >> 3;
            int grp = p >> 6, e = p & 7;
            const uint32_t* qp = Qh + rowq * 68;
            const float* kp = KVf + (grp * 8 + e) * 136;
            float s = 0.f;
#pragma unroll 8
            for (int kw = 0; kw < 64; kw += 2) {
                float2 q0 = unp2(qp[kw]);
                float2 q1 = unp2(qp[kw + 1]);
                float4 kv = *(const float4*)&kp[2 * kw];
                s += q0.x * kv.x + q0.y * kv.y + q1.x * kv.z + q1.y * kv.w;
            }
            sc[p] = s * 0.088388347648318447f;
        }
    }
    __syncthreads();
    if (tid < 64) {    // softmax over e per (grp,c)
        float* row = sc + tid * 8;
        float m = row[0];
#pragma unroll
        for (int e = 1; e < 8; e++) m = fmaxf(m, row[e]);
        float ex[8], ssum = 0.f;
#pragma unroll
        for (int e = 0; e < 8; e++) { ex[e] = expf(row[e] - m); ssum += ex[e]; }
        float inv = 1.0f / ssum;
#pragma unroll
        for (int e = 0; e < 8; e++) row[e] = ex[e] * inv;
    }
    cp_wait<0>();                             // wv arrived
    __syncthreads();
    {   // V gemm -> regs, then overwrite KVf (K dead: scores synced)
        float acc[8][4];
        zero_acc(&acc[0][0], 32);
        gemm_h<68, 68, 8>(acc, As, W, mbase, nbase, 64, q, t);
        __syncthreads();                      // all K reads done
#pragma unroll
        for (int nt = 0; nt < 8; nt++) {
            int rr = mbase + q, cc = nbase + nt * 8 + 2 * t;
            float b0 = bv[cc], b1 = bv[cc + 1];
            KVf[rr * 136 + cc]           = acc[nt][0] + b0;
            KVf[rr * 136 + cc + 1]       = acc[nt][1] + b1;
            KVf[(rr + 8) * 136 + cc]     = acc[nt][2] + b0;
            KVf[(rr + 8) * 136 + cc + 1] = acc[nt][3] + b1;
        }
    }
    __syncthreads();                          // V final; W(wv)/As reads done
    cpy68<256>(W, gw_qkvo + 24576, 128, tid); // wo (overlaps o-compute)
    cp_commit();
    {   // o = attn @ V -> As fp16, in place
        int rr = tid >> 2, d0 = (tid & 3) * 32;
        const float* vb = KVf + (rr & ~7) * 136;
        float a[8];
#pragma unroll
        for (int e = 0; e < 8; e++) a[e] = sc[rr * 8 + e];
        uint32_t* ar = As + rr * 68 + (d0 >> 1);
#pragma unroll
        for (int j = 0; j < 32; j += 4) {
            float4 o = make_float4(0.f, 0.f, 0.f, 0.f);
#pragma unroll
            for (int e = 0; e < 8; e++) {
                float4 v = *(const float4*)&vb[e * 136 + d0 + j];
                o.x += a[e] * v.x; o.y += a[e] * v.y;
                o.z += a[e] * v.z; o.w += a[e] * v.w;
            }
            ar[(j >> 1)]     = pack2(o.x, o.y);
            ar[(j >> 1) + 1] = pack2(o.z, o.w);
        }
    }
    cp_wait<0>();                             // wo arrived
    __syncthreads();                          // As(o) final
    {   // wo gemm + residual -> g_xa
        float acc[8][4];
        zero_acc(&acc[0][0], 32);
        gemm_h<68, 68, 8>(acc, As, W, mbase, nbase, 64, q, t);
#pragma unroll
        for (int nt = 0; nt < 8; nt++) {
            int rr = mbase + q, cc = nbase + nt * 8 + 2 * t;
            float b0 = bo[cc], b1 = bo[cc + 1];
            size_t o0 = (rowbase + rr) * 128 + cc;
            size_t o1 = (rowbase + rr + 8) * 128 + cc;
            float2 x0 = *(const float2*)&x[o0];
            float2 x1 = *(const float2*)&x[o1];
            *(float2*)&g_xa[o0] = make_float2(x0.x + acc[nt][0] + b0,
                                              x0.y + acc[nt][1] + b1);
            *(float2*)&g_xa[o1] = make_float2(x1.x + acc[nt][2] + b0,
                                              x1.y + acc[nt][3] + b1);
        }
    }
}

// ===========================================================================
// K2: mega per-group kernel, 64-token tiles, 256 thr, 2 CTAs/SM.
// grid (32, 64). words: As 4352 | Zs 2304 | Ds 2304 | B0 8704 | B1 8704 | 256
// ===========================================================================
__global__ __launch_bounds__(256, 2)
void k_mega(const float* __restrict__ zhp,
            const float* __restrict__ lng, const float* __restrict__ lnb,
            const float* __restrict__ encb, const float* __restrict__ predb,
            const float* __restrict__ gainb, const float* __restrict__ upb,
            const float* __restrict__ dwb, const float* __restrict__ pb,
            float* out) {
    extern __shared__ uint32_t sm[];
    uint32_t* As = sm;                  // 64 x 68 (half)
    uint32_t* Zs = As + 4352;           // 64 x 36 (half)
    uint32_t* Ds = Zs + 2304;           // 64 x 36 (half)
    uint32_t* B0 = Ds + 2304;           // 8704
    uint32_t* B1 = B0 + 8704;           // 8704
    float* smu = (float*)(B1 + 8704);   // 64
    float* srs = smu + 64;              // 64
    float* pr  = srs + 64;              // 128
    const int tid = threadIdx.x;
    const int g = blockIdx.y, p0 = blockIdx.x * 64;

    cpy68<256>(B0, gw_enc + (size_t)g * 4096, 64, tid);   cp_commit();
    cpy36<256>(B1, gw_pred + (size_t)g * 2048, 64, tid);  cp_commit();

    {   // As = fp16(x_attn), stats
        const int r = tid >> 2, h = tid & 3;
        const float* xr = g_xa + ((size_t)(p0 + r) * 64 + g) * 128 + h * 32;
        float xv[32];
        float s = 0.f, s2 = 0.f;
#pragma unroll
        for (int j = 0; j < 32; j += 4) {
            float4 v = *(const float4*)&xr[j];
            xv[j] = v.x; xv[j + 1] = v.y; xv[j + 2] = v.z; xv[j + 3] = v.w;
            s += v.x + v.y + v.z + v.w;
            s2 += v.x * v.x + v.y * v.y + v.z * v.z + v.w * v.w;
        }
        uint32_t* ar = As + r * 68 + h * 16;
#pragma unroll
        for (int j = 0; j < 32; j += 2)
            ar[j >> 1] = pack2(xv[j], xv[j + 1]);
        s  += __shfl_xor_sync(0xffffffffu, s, 1);
        s  += __shfl_xor_sync(0xffffffffu, s, 2);
        s2 += __shfl_xor_sync(0xffffffffu, s2, 1);
        s2 += __shfl_xor_sync(0xffffffffu, s2, 2);
        float mu = s * (1.f / 128.f);
        if (h == 0) {
            smu[r] = mu;
            srs[r] = rsqrtf(s2 * (1.f / 128.f) - mu * mu + 1e-5f);
        }
    }
    cp_wait<1>();     // enc ready
    __syncthreads();

    const int w = tid >> 5, lane = tid & 31, q = lane >> 2, t = lane & 3;
    const int mbase = (w & 3) * 16, wn = w >> 2;

    {   // enc GEMM (16 x 32 per warp, Kw=64)
        float acc[4][4];
        zero_acc(&acc[0][0], 16);
        gemm_h<68, 68, 4>(acc, As, B0, mbase, wn * 32, 64, q, t);
        float sl = 0.f, sh = 0.f;
#pragma unroll
        for (int nt = 0; nt < 4; nt++) {
            int cc = wn * 32 + nt * 8 + 2 * t;
            int rlo = mbase + q, rhi = rlo + 8;
            float z0 = acc[nt][0] + encb[g * 64 + cc];
            float z1 = acc[nt][1] + encb[g * 64 + cc + 1];
            float z2 = acc[nt][2] + encb[g * 64 + cc];
            float z3 = acc[nt][3] + encb[g * 64 + cc + 1];
            size_t qlo = (size_t)(p0 + rlo) * 64 + g;
            size_t qhi = (size_t)(p0 + rhi) * 64 + g;
            *(float2*)&out[OFF_Z + qlo * 64 + cc] = make_float2(z0, z1);
            *(float2*)&out[OFF_Z + qhi * 64 + cc] = make_float2(z2, z3);
            float2 plo = *(const float2*)&zhp[qlo * 64 + cc];
            float2 phi = *(const float2*)&zhp[qhi * 64 + cc];
            float d0 = z0 - plo.x, d1 = z1 - plo.y;
            float d2 = z2 - phi.x, d3 = z3 - phi.y;
            int wi = cc >> 1;
            Zs[rlo * 36 + wi] = pack2(z0, z1);
            Zs[rhi * 36 + wi] = pack2(z2, z3);
            Ds[rlo * 36 + wi] = pack2(d0, d1);
            Ds[rhi * 36 + wi] = pack2(d2, d3);
            sl += d0 * d0 + d1 * d1;
            sh += d2 * d2 + d3 * d3;
        }
        sl += __shfl_xor_sync(0xffffffffu, sl, 1);
        sl += __shfl_xor_sync(0xffffffffu, sl, 2);
        sh += __shfl_xor_sync(0xffffffffu, sh, 1);
        sh += __shfl_xor_sync(0xffffffffu, sh, 2);
        if (t == 0) {
            pr[wn * 64 + mbase + q] = sl;
            pr[wn * 64 + mbase + q + 8] = sh;
        }
    }
    __syncthreads();
    if (tid < 64) {   // surprise + gate
        float sp = sqrtf(pr[tid] + pr[64 + tid]);
        size_t qq = (size_t)(p0 + tid) * 64 + g;
        out[OFF_S + qq] = sp;
        out[OFF_G + qq] = fminf(sp, 1.0f);
    }
    cpy68<256>(B0, gw_up + (size_t)g * 32768, 128, tid);     cp_commit();   // up0
    cp_wait<1>();                                            // pred ready
    __syncthreads();
    {   // pred GEMM (Kw=32)
        float acc[4][4];
        zero_acc(&acc[0][0], 16);
        gemm_h<36, 36, 4>(acc, Zs, B1, mbase, wn * 32, 32, q, t);
#pragma unroll
        for (int nt = 0; nt < 4; nt++) {
            int cc = wn * 32 + nt * 8 + 2 * t;
            size_t qlo = (size_t)(p0 + mbase + q) * 64 + g;
            size_t qhi = (size_t)(p0 + mbase + q + 8) * 64 + g;
            float b0 = predb[g * 64 + cc], b1 = predb[g * 64 + cc + 1];
            *(float2*)&out[OFF_ZH + qlo * 64 + cc] =
                make_float2(acc[nt][0] + b0, acc[nt][1] + b1);
            *(float2*)&out[OFF_ZH + qhi * 64 + cc] =
                make_float2(acc[nt][2] + b0, acc[nt][3] + b1);
        }
    }
    __syncthreads();
    cpy36<256>(B1, gw_gain + (size_t)g * 4096, 128, tid);    cp_commit();   // gain
    cp_wait<0>();
    __syncthreads();
    {   // gain GEMM (16x64 per warp, Kw=32) + GLN epilogue -> As := fp16(hh)
        float acc[8][4];
        zero_acc(&acc[0][0], 32);
        gemm_h<36, 36, 8>(acc, Ds, B1, mbase, wn * 64, 32, q, t);
        int rlo = mbase + q, rhi = rlo + 8;
        float mlo = smu[rlo], rslo = srs[rlo];
        float mhi = smu[rhi], rshi = srs[rhi];
#pragma unroll
        for (int nt = 0; nt < 8; nt++) {
            int cc = wn * 64 + nt * 8 + 2 * t, wi = cc >> 1;
            float lg0 = lng[(size_t)g * 128 + cc], lb0 = lnb[(size_t)g * 128 + cc];
            float lg1 = lng[(size_t)g * 128 + cc + 1], lb1 = lnb[(size_t)g * 128 + cc + 1];
            float gb0 = gainb[(size_t)g * 128 + cc], gb1 = gainb[(size_t)g * 128 + cc + 1];
            float2 xlo = unp2(As[rlo * 68 + wi]);
            float2 xhi = unp2(As[rhi * 68 + wi]);
            float h00 = ((xlo.x - mlo) * rslo * lg0 + lb0)
                        * (1.0f + 0.1f * tanhf(acc[nt][0] + gb0));
            float h01 = ((xlo.y - mlo) * rslo * lg1 + lb1)
                        * (1.0f + 0.1f * tanhf(acc[nt][1] + gb1));
            float h10 = ((xhi.x - mhi) * rshi * lg0 + lb0)
                        * (1.0f + 0.1f * tanhf(acc[nt][2] + gb0));
            float h11 = ((xhi.y - mhi) * rshi * lg1 + lb1)
                        * (1.0f + 0.1f * tanhf(acc[nt][3] + gb1));
            As[rlo * 68 + wi] = pack2(h00, h01);
            As[rhi * 68 + wi] = pack2(h10, h11);
        }
    }
    __syncthreads();
    cpy68<256>(B1, gw_down + (size_t)g * 32768, 128, tid);   cp_commit();   // down0

    uint32_t* Us = Zs;   // 64 x 68 overlays Zs+Ds
    float oacc[8][4];
    zero_acc(&oacc[0][0], 32);
    for (int ch = 0; ch < 4; ch++) {
        float uacc[8][4];
        zero_acc(&uacc[0][0], 32);
        gemm_h<68, 68, 8>(uacc, As, B0, mbase, wn * 64, 64, q, t);
#pragma unroll
        for (int nt = 0; nt < 8; nt++) {
            int cc = wn * 64 + nt * 8 + 2 * t, wi = cc >> 1;
            int rlo = mbase + q, rhi = rlo + 8;
            float b0 = upb[(size_t)g * 512 + ch * 128 + cc];
            float b1 = upb[(size_t)g * 512 + ch * 128 + cc + 1];
            float u00 = uacc[nt][0] + b0, u01 = uacc[nt][1] + b1;
            float u10 = uacc[nt][2] + b0, u11 = uacc[nt][3] + b1;
            u00 = 0.5f * u00 * (1.0f + erff(u00 * 0.70710678118654752f));
            u01 = 0.5f * u01 * (1.0f + erff(u01 * 0.70710678118654752f));
            u10 = 0.5f * u10 * (1.0f + erff(u10 * 0.70710678118654752f));
            u11 = 0.5f * u11 * (1.0f + erff(u11 * 0.70710678118654752f));
            Us[rlo * 68 + wi] = pack2(u00, u01);
            Us[rhi * 68 + wi] = pack2(u10, u11);
        }
        __syncthreads();
        if (ch < 3) {
            cpy68<256>(B0, gw_up + (size_t)g * 32768 + (ch + 1) * 8192, 128, tid);
            cp_commit();
            cp_wait<1>();
        } else {
            cp_wait<0>();
        }
        __syncthreads();
        gemm_h<68, 68, 8>(oacc, Us, B1, mbase, wn * 64, 64, q, t);
        if (ch < 3) {
            __syncthreads();
            cpy68<256>(B1, gw_down + (size_t)g * 32768 + (ch + 1) * 8192, 128, tid);
            cp_commit();
            cp_wait<1>();
            __syncthreads();
        }
    }
    __syncthreads();
    {   // MLP epilogue -> gmem x_out AND As := fp16(x_out)
#pragma unroll
        for (int nt = 0; nt < 8; nt++) {
            int cc = wn * 64 + nt * 8 + 2 * t, wi = cc >> 1;
            int rlo = mbase + q, rhi = rlo + 8;
            float b0 = dwb[(size_t)g * 128 + cc], b1 = dwb[(size_t)g * 128 + cc + 1];
            size_t o0 = ((size_t)(p0 + rlo) * 64 + g) * 128 + cc;
            size_t o1 = ((size_t)(p0 + rhi) * 64 + g) * 128 + cc;
            float2 x0 = *(const float2*)&g_xa[o0];
            float2 x1 = *(const float2*)&g_xa[o1];
            float v00 = x0.x + oacc[nt][0] + b0, v01 = x0.y + oacc[nt][1] + b1;
            float v10 = x1.x + oacc[nt][2] + b0, v11 = x1.y + oacc[nt][3] + b1;
            *(float2*)&out[OFF_XOUT + o0] = make_float2(v00, v01);
            *(float2*)&out[OFF_XOUT + o1] = make_float2(v10, v11);
            As[rlo * 68 + wi] = pack2(v00, v01);
            As[rhi * 68 + wi] = pack2(v10, v11);
        }
    }
    __syncthreads();
    cpy68<256>(B0, gw_post + (size_t)g * 32768, 128, tid);         cp_commit();
    cpy68<256>(B1, gw_post + (size_t)g * 32768 + 8192, 128, tid);  cp_commit();

    if (tid < 64) {   // w_nov
        const float* wl = gw_plast + g * 128;
        float s = 0.f;
        for (int kw = 0; kw < 64; kw++) {
            float2 xv = unp2(As[tid * 68 + kw]);
            s += xv.x * wl[2 * kw] + xv.y * wl[2 * kw + 1];
        }
        s += pb[(size_t)g * 513 + 512];
        out[OFF_WN + (size_t)(p0 + tid) * 64 + g] = 1.0f / (1.0f + expf(-s));
    }

    for (int ch = 0; ch < 4; ch++) {
        if (ch < 3) cp_wait<1>(); else cp_wait<0>();
        __syncthreads();
        uint32_t* Bs = (ch & 1) ? B1 : B0;
        float acc[8][4];
        zero_acc(&acc[0][0], 32);
        gemm_h<68, 68, 8>(acc, As, Bs, mbase, wn * 64, 64, q, t);
#pragma unroll
        for (int nt = 0; nt < 8; nt++) {
            int cc = wn * 64 + nt * 8 + 2 * t;
            float b0 = pb[(size_t)g * 513 + ch * 128 + cc];
            float b1 = pb[(size_t)g * 513 + ch * 128 + cc + 1];
            acc[nt][0] += b0; acc[nt][1] += b1;
            acc[nt][2] += b0; acc[nt][3] += b1;
        }
        if (ch == 1 || ch == 3) {
            size_t off = (ch == 1) ? OFF_VP : OFF_VC;
#pragma unroll
            for (int nt = 0; nt < 8; nt++) {
                int rr = mbase + q, cc = wn * 64 + nt * 8 + 2 * t;
                size_t o0 = off + ((size_t)(p0 + rr) * 64 + g) * 128 + cc;
                size_t o1 = off + ((size_t)(p0 + rr + 8) * 64 + g) * 128 + cc;
                *(float2*)&out[o0] = make_float2(acc[nt][0], acc[nt][1]);
                *(float2*)&out[o1] = make_float2(acc[nt][2], acc[nt][3]);
            }
        } else {
            float sl = 0.f, sh = 0.f;
#pragma unroll
            for (int nt = 0; nt < 8; nt++) {
                sl += acc[nt][0] * acc[nt][0] + acc[nt][1] * acc[nt][1];
                sh += acc[nt][2] * acc[nt][2] + acc[nt][3] * acc[nt][3];
            }
            sl += __shfl_xor_sync(0xffffffffu, sl, 1);
            sl += __shfl_xor_sync(0xffffffffu, sl, 2);
            sh += __shfl_xor_sync(0xffffffffu, sh, 1);
            sh += __shfl_xor_sync(0xffffffffu, sh, 2);
            if (t == 0) {
                pr[wn * 64 + mbase + q] = sl;
                pr[wn * 64 + mbase + q + 8] = sh;
            }
            __syncthreads();
            size_t off = (ch == 0) ? OFF_KC : OFF_QN;
#pragma unroll
            for (int nt = 0; nt < 8; nt++) {
                int rr = mbase + q, cc = wn * 64 + nt * 8 + 2 * t;
                float i0 = 1.0f / fmaxf(sqrtf(pr[rr] + pr[64 + rr]), 1e-6f);
                float i1 = 1.0f / fmaxf(sqrtf(pr[rr + 8] + pr[64 + rr + 8]), 1e-6f);
                size_t o0 = off + ((size_t)(p0 + rr) * 64 + g) * 128 + cc;
                size_t o1 = off + ((size_t)(p0 + rr + 8) * 64 + g) * 128 + cc;
                *(float2*)&out[o0] = make_float2(acc[nt][0] * i0, acc[nt][1] * i0);
                *(float2*)&out[o1] = make_float2(acc[nt][2] * i1, acc[nt][3] * i1);
            }
        }
        if (ch < 2) {
            __syncthreads();
            cpy68<256>((ch & 1) ? B1 : B0,
                       gw_post + (size_t)g * 32768 + (ch + 2) * 8192, 128, tid);
            cp_commit();
        }
    }
}

// ===========================================================================
extern "C" void kernel_launch(void* const* d_in, const int* in_sizes, int n_in,
                              void* d_out, int out_size) {
    const float* x_col  = (const float*)d_in[0];
    const float* zhp    = (const float*)d_in[1];
    const float* ln_g   = (const float*)d_in[2];
    const float* ln_b   = (const float*)d_in[3];
    const float* up_w   = (const float*)d_in[4];
    const float* up_b   = (const float*)d_in[5];
    const float* down_w = (const float*)d_in[6];
    const float* down_b = (const float*)d_in[7];
    const float* lat_g  = (const float*)d_in[8];
    const float* lat_b  = (const float*)d_in[9];
    const float* wq     = (const float*)d_in[10];
    const float* bq     = (const float*)d_in[11];
    const float* wk     = (const float*)d_in[12];
    const float* bk     = (const float*)d_in[13];
    const float* wv     = (const float*)d_in[14];
    const float* bv     = (const float*)d_in[15];
    const float* wo     = (const float*)d_in[16];
    const float* bo     = (const float*)d_in[17];
    const float* post_w = (const float*)d_in[18];
    const float* post_b = (const float*)d_in[19];
    const float* enc_w  = (const float*)d_in[20];
    const float* enc_b  = (const float*)d_in[21];
    const float* pred_w = (const float*)d_in[22];
    const float* pred_b = (const float*)d_in[23];
    const float* gain_w = (const float*)d_in[24];
    const float* gain_b = (const float*)d_in[25];
    float* out = (float*)d_out;

    const int SM_FA   = 26880 * 4;   // 107520  (2 CTAs/SM)
    const int SM_MEGA = 26624 * 4;   // 106496  (2 CTAs/SM)

    cudaFuncSetAttribute(k_fattn, cudaFuncAttributeMaxDynamicSharedMemorySize, SM_FA);
    cudaFuncSetAttribute(k_mega,  cudaFuncAttributeMaxDynamicSharedMemorySize, SM_MEGA);

    uint32_t* d_enc;  cudaGetSymbolAddress((void**)&d_enc,  gw_enc);
    uint32_t* d_pred; cudaGetSymbolAddress((void**)&d_pred, gw_pred);
    uint32_t* d_gain; cudaGetSymbolAddress((void**)&d_gain, gw_gain);
    uint32_t* d_up;   cudaGetSymbolAddress((void**)&d_up,   gw_up);
    uint32_t* d_down; cudaGetSymbolAddress((void**)&d_down, gw_down);
    uint32_t* d_post; cudaGetSymbolAddress((void**)&d_post, gw_post);

    k_tcvt_qkvo2<<<dim3(4, 4, 4), 256>>>(wq, wk, wv, wo);
    k_tcvt2<<<dim3(4, 2, 64), 256>>>(enc_w, d_enc, 8192, 64, 4096,
                                     6, 0, 7, 0, 63, 64, 127);
    k_tcvt2<<<dim3(2, 2, 64), 256>>>(pred_w, d_pred, 4096, 64, 2048,
                                     6, 0, 6, 0, 63, 32, 63);
    k_tcvt2<<<dim3(2, 4, 64), 256>>>(gain_w, d_gain, 8192, 128, 4096,
                                     7, 0, 6, 0, 127, 32, 63);
    k_tcvt2<<<dim3(4, 16, 64), 256>>>(up_w, d_up, 65536, 512, 32768,
                                      7, 8192, 7, 0, 127, 64, 127);
    k_tcvt2<<<dim3(16, 4, 64), 256>>>(down_w, d_down, 65536, 128, 32768,
                                      7, 0, 7, 8192, 127, 64, 127);
    k_tcvt2<<<dim3(4, 16, 64), 256>>>(post_w, d_post, 65664, 513, 32768,
                                      7, 8192, 7, 0, 127, 64, 127);
    k_plast<<<32, 256>>>(post_w);

    k_fattn<<<R_TOT / 64, 256, SM_FA>>>(x_col, lat_g, lat_b, bq, bk, bv, bo);
    k_mega<<<dim3(TOKS / 64, 64), 256, SM_MEGA>>>(zhp, ln_g, ln_b,
                                                  enc_b, pred_b, gain_b,
                                                  up_b, down_b, post_b, out);
}

// round 17
// speedup vs baseline: 1.0179x; 1.0156x over previous
#include <cuda_runtime.h>
#include <cuda_fp16.h>
#include <math.h>
#include <stdint.h>

#define R_TOT 131072   // BS*N*G rows
#define TOKS  2048     // BS*N tokens

static constexpr size_t OFF_XOUT = 0;
static constexpr size_t OFF_Z    = 16777216;
static constexpr size_t OFF_ZH   = 25165824;
static constexpr size_t OFF_S    = 33554432;
static constexpr size_t OFF_KC   = 33685504;
static constexpr size_t OFF_VP   = 50462720;
static constexpr size_t OFF_G    = 67239936;
static constexpr size_t OFF_QN   = 67371008;
static constexpr size_t OFF_VC   = 84148224;
static constexpr size_t OFF_WN   = 100925440;

// Scratch
__device__ float g_xa[16777216];
__device__ int   g_ticket;
__device__ int   g_done[2048];

// fp16 weights (half2-packed uint32), n-major [n][k]
__device__ uint32_t gw_qkvo[32768];
__device__ uint32_t gw_enc [262144];
__device__ uint32_t gw_pred[131072];
__device__ uint32_t gw_gain[262144];
__device__ uint32_t gw_up  [2097152];
__device__ uint32_t gw_down[2097152];
__device__ uint32_t gw_post[2097152];
__device__ float    gw_plast[8192];

// ===========================================================================
__device__ __forceinline__ uint32_t pack2(float lo, float hi) {
    uint32_t r;
    asm("cvt.rn.f16x2.f32 %0, %1, %2;" : "=r"(r) : "f"(hi), "f"(lo));
    return r;
}
__device__ __forceinline__ float2 unp2(uint32_t v) {
    __half2 h = *reinterpret_cast<__half2*>(&v);
    return __half22float2(h);
}
__device__ __forceinline__ void mma_h(float* c, uint32_t a0, uint32_t a1,
                                      uint32_t a2, uint32_t a3,
                                      uint32_t b0, uint32_t b1) {
    asm volatile(
        "mma.sync.aligned.m16n8k16.row.col.f32.f16.f16.f32 "
        "{%0,%1,%2,%3}, {%4,%5,%6,%7}, {%8,%9}, {%0,%1,%2,%3};"
        : "+f"(c[0]), "+f"(c[1]), "+f"(c[2]), "+f"(c[3])
        : "r"(a0), "r"(a1), "r"(a2), "r"(a3), "r"(b0), "r"(b1));
}
__device__ __forceinline__ void cp16(void* smem, const void* gmem) {
    uint32_t s = (uint32_t)__cvta_generic_to_shared(smem);
    asm volatile("cp.async.cg.shared.global [%0], [%1], 16;" :: "r"(s), "l"(gmem));
}
__device__ __forceinline__ void cp_commit() {
    asm volatile("cp.async.commit_group;" ::: "memory");
}
template<int N> __device__ __forceinline__ void cp_wait() {
    asm volatile("cp.async.wait_group %0;" :: "n"(N) : "memory");
}
__device__ __forceinline__ void cpy68(uint32_t* dst, const uint32_t* src,
                                      int rows, int tid) {
    for (int i = tid; i < rows * 16; i += 256) {
        int r = i >> 4, c = (i & 15) * 4;
        cp16(dst + r * 68 + c, src + r * 64 + c);
    }
}
__device__ __forceinline__ void cpy36(uint32_t* dst, const uint32_t* src,
                                      int rows, int tid) {
    for (int i = tid; i < rows * 8; i += 256) {
        int r = i >> 3, c = (i & 7) * 4;
        cp16(dst + r * 36 + c, src + r * 32 + c);
    }
}
template<int LDA, int LDB, int NT>
__device__ __forceinline__ void gemm_h(float acc[NT][4],
        const uint32_t* __restrict__ As, const uint32_t* __restrict__ Bs,
        int mbase, int nbase, int Kw, int q, int t) {
#pragma unroll 2
    for (int kw = 0; kw < Kw; kw += 8) {
        const uint32_t* ap0 = As + (mbase + q) * LDA + kw + t;
        const uint32_t* ap1 = As + (mbase + q + 8) * LDA + kw + t;
        uint32_t a0 = ap0[0], a2 = ap0[4];
        uint32_t a1 = ap1[0], a3 = ap1[4];
#pragma unroll
        for (int nt = 0; nt < NT; nt++) {
            const uint32_t* bp = Bs + (nbase + nt * 8 + q) * LDB + kw + t;
            mma_h(acc[nt], a0, a1, a2, a3, bp[0], bp[4]);
        }
    }
}
__device__ __forceinline__ void zero_acc(float* a, int n) {
#pragma unroll
    for (int i = 0; i < n; i++) a[i] = 0.f;
}

// ===========================================================================
// Weight prep
// ===========================================================================
__global__ void k_reset() {
    int i = blockIdx.x * 256 + threadIdx.x;
    if (i == 0) g_ticket = 0;
    if (i < 2048) g_done[i] = 0;
}
__global__ void k_tcvt2(const float* __restrict__ src, uint32_t* __restrict__ dst,
                        long sgs, int sld, long gs,
                        int ns, int nchs, int ks, int kchs,
                        int cm, int ldn, int km) {
    __shared__ float tile[32][33];
    int g = blockIdx.z;
    int k0 = blockIdx.x * 32, n0 = blockIdx.y * 32;
    int tr = threadIdx.x >> 5, tc = threadIdx.x & 31;
    const float* s = src + (size_t)g * sgs;
#pragma unroll
    for (int i = 0; i < 4; i++)
        tile[tr + i * 8][tc] = s[(size_t)(k0 + tr + i * 8) * sld + n0 + tc];
    __syncthreads();
    uint32_t* d = dst + (size_t)g * gs;
    int np = threadIdx.x >> 4, kp = threadIdx.x & 15;
#pragma unroll
    for (int ii = 0; ii < 2; ii++) {
        int n = n0 + np + ii * 16, k = k0 + 2 * kp;
        uint32_t v = pack2(tile[2 * kp][np + ii * 16], tile[2 * kp + 1][np + ii * 16]);
        d[(size_t)(n >> ns) * nchs + (size_t)(k >> ks) * kchs
          + (n & cm) * ldn + ((k & km) >> 1)] = v;
    }
}
__global__ void k_tcvt_qkvo2(const float* __restrict__ wq, const float* __restrict__ wk,
                             const float* __restrict__ wv, const float* __restrict__ wo) {
    __shared__ float tile[32][33];
    int sel = blockIdx.z;
    const float* s = (sel == 0) ? wq : (sel == 1) ? wk : (sel == 2) ? wv : wo;
    int k0 = blockIdx.x * 32, n0 = blockIdx.y * 32;
    int tr = threadIdx.x >> 5, tc = threadIdx.x & 31;
#pragma unroll
    for (int i = 0; i < 4; i++)
        tile[tr + i * 8][tc] = s[(size_t)(k0 + tr + i * 8) * 128 + n0 + tc];
    __syncthreads();
    uint32_t* d = gw_qkvo + sel * 8192;
    int np = threadIdx.x >> 4, kp = threadIdx.x & 15;
#pragma unroll
    for (int ii = 0; ii < 2; ii++) {
        int n = n0 + np + ii * 16, k = k0 + 2 * kp;
        d[n * 64 + (k >> 1)] =
            pack2(tile[2 * kp][np + ii * 16], tile[2 * kp + 1][np + ii * 16]);
    }
}
__global__ void k_plast(const float* __restrict__ pw) {
    int i = blockIdx.x * 256 + threadIdx.x;
    if (i < 8192)
        gw_plast[i] = pw[(size_t)i * 513 + 512];
}

// ===========================================================================
// Combined kernel: tickets 0..2047 = fattn token tiles; 2048.. = mega tiles.
// 256 thr, 2 CTAs/SM, smem 26880 words (fattn layout is the max).
// ===========================================================================
__global__ __launch_bounds__(256, 2)
void k_all(const float* __restrict__ x,
           const float* __restrict__ latg, const float* __restrict__ latb,
           const float* __restrict__ bq, const float* __restrict__ bk,
           const float* __restrict__ bv, const float* __restrict__ bo,
           const float* __restrict__ zhp,
           const float* __restrict__ lng, const float* __restrict__ lnb,
           const float* __restrict__ encb, const float* __restrict__ predb,
           const float* __restrict__ gainb, const float* __restrict__ upb,
           const float* __restrict__ dwb, const float* __restrict__ pb,
           float* out) {
    extern __shared__ uint32_t sm[];
    __shared__ int stk;
    const int tid = threadIdx.x;
    if (tid == 0) stk = atomicAdd(&g_ticket, 1);
    __syncthreads();
    const int tk = stk;

    if (tk < 2048) {
        // =============== fattn tile: token tk (64 rows) ===============
        uint32_t* As = sm;                   // 64 x 68 (half)
        uint32_t* W  = As + 4352;            // 128 x 68 (half)
        uint32_t* Qh = W + 8704;             // 64 x 68 (half)
        float* KVf = (float*)(Qh + 4352);    // 64 x 136 fp32
        float* sc = KVf + 8704;              // 512
        float* sg = sc + 512;                // 128
        float* sb = sg + 128;                // 128
        const size_t rowbase = (size_t)tk * 64;

        cpy68(W, gw_qkvo, 128, tid);  cp_commit();  // wq

        if (tid < 128) { sg[tid] = latg[tid]; sb[tid] = latb[tid]; }
        {   // LN -> As fp16
            const int r = tid >> 2, h = tid & 3;
            const float* xr = x + (rowbase + r) * 128 + h * 32;
            float xv[32];
            float s = 0.f, s2 = 0.f;
#pragma unroll
            for (int j = 0; j < 32; j += 4) {
                float4 v = *(const float4*)&xr[j];
                xv[j] = v.x; xv[j + 1] = v.y; xv[j + 2] = v.z; xv[j + 3] = v.w;
                s += v.x + v.y + v.z + v.w;
                s2 += v.x * v.x + v.y * v.y + v.z * v.z + v.w * v.w;
            }
            s  += __shfl_xor_sync(0xffffffffu, s, 1);
            s  += __shfl_xor_sync(0xffffffffu, s, 2);
            s2 += __shfl_xor_sync(0xffffffffu, s2, 1);
            s2 += __shfl_xor_sync(0xffffffffu, s2, 2);
            float mu = s * (1.f / 128.f);
            float rs = rsqrtf(s2 * (1.f / 128.f) - mu * mu + 1e-5f);
            __syncthreads();
            uint32_t* ar = As + r * 68 + h * 16;
#pragma unroll
            for (int j = 0; j < 32; j += 2) {
                int c = h * 32 + j;
                float h0 = (xv[j] - mu) * rs * sg[c] + sb[c];
                float h1 = (xv[j + 1] - mu) * rs * sg[c + 1] + sb[c + 1];
                ar[j >> 1] = pack2(h0, h1);
            }
        }
        __syncthreads();
        cp_wait<0>();
        __syncthreads();

        const int w = tid >> 5, lane = tid & 31, q = lane >> 2, t = lane & 3;
        const int mbase = (w & 3) * 16, nbase = (w >> 2) * 64;

        {   // Q gemm -> Qh fp16
            float acc[8][4];
            zero_acc(&acc[0][0], 32);
            gemm_h<68, 68, 8>(acc, As, W, mbase, nbase, 64, q, t);
#pragma unroll
            for (int nt = 0; nt < 8; nt++) {
                int rr = mbase + q, cc = nbase + nt * 8 + 2 * t, wi = cc >> 1;
                float b0 = bq[cc], b1 = bq[cc + 1];
                Qh[rr * 68 + wi]       = pack2(acc[nt][0] + b0, acc[nt][1] + b1);
                Qh[(rr + 8) * 68 + wi] = pack2(acc[nt][2] + b0, acc[nt][3] + b1);
            }
        }
        __syncthreads();
        cpy68(W, gw_qkvo + 8192, 128, tid);  // wk
        cp_commit();
        cp_wait<0>();
        __syncthreads();
        {   // K gemm -> KVf fp32
            float acc[8][4];
            zero_acc(&acc[0][0], 32);
            gemm_h<68, 68, 8>(acc, As, W, mbase, nbase, 64, q, t);
#pragma unroll
            for (int nt = 0; nt < 8; nt++) {
                int rr = mbase + q, cc = nbase + nt * 8 + 2 * t;
                float b0 = bk[cc], b1 = bk[cc + 1];
                KVf[rr * 136 + cc]           = acc[nt][0] + b0;
                KVf[rr * 136 + cc + 1]       = acc[nt][1] + b1;
                KVf[(rr + 8) * 136 + cc]     = acc[nt][2] + b0;
                KVf[(rr + 8) * 136 + cc + 1] = acc[nt][3] + b1;
            }
        }
        __syncthreads();
        cpy68(W, gw_qkvo + 16384, 128, tid); // wv (overlaps scores)
        cp_commit();
        {   // scores
#pragma unroll
            for (int i = 0; i < 2; i++) {
                int p = tid + 256 * i;
                int rowq = p >> 3;
                int grp = p >> 6, e = p & 7;
                const uint32_t* qp = Qh + rowq * 68;
                const float* kp = KVf + (grp * 8 + e) * 136;
                float s = 0.f;
#pragma unroll 8
                for (int kw = 0; kw < 64; kw += 2) {
                    float2 q0 = unp2(qp[kw]);
                    float2 q1 = unp2(qp[kw + 1]);
                    float4 kv = *(const float4*)&kp[2 * kw];
                    s += q0.x * kv.x + q0.y * kv.y + q1.x * kv.z + q1.y * kv.w;
                }
                sc[p] = s * 0.088388347648318447f;
            }
        }
        __syncthreads();
        if (tid < 64) {    // softmax
            float* row = sc + tid * 8;
            float m = row[0];
#pragma unroll
            for (int e = 1; e < 8; e++) m = fmaxf(m, row[e]);
            float ex[8], ssum = 0.f;
#pragma unroll
            for (int e = 0; e < 8; e++) { ex[e] = expf(row[e] - m); ssum += ex[e]; }
            float inv = 1.0f / ssum;
#pragma unroll
            for (int e = 0; e < 8; e++) row[e] = ex[e] * inv;
        }
        cp_wait<0>();
        __syncthreads();
        {   // V gemm -> regs -> overwrite KVf
            float acc[8][4];
            zero_acc(&acc[0][0], 32);
            gemm_h<68, 68, 8>(acc, As, W, mbase, nbase, 64, q, t);
            __syncthreads();
#pragma unroll
            for (int nt = 0; nt < 8; nt++) {
                int rr = mbase + q, cc = nbase + nt * 8 + 2 * t;
                float b0 = bv[cc], b1 = bv[cc + 1];
                KVf[rr * 136 + cc]           = acc[nt][0] + b0;
                KVf[rr * 136 + cc + 1]       = acc[nt][1] + b1;
                KVf[(rr + 8) * 136 + cc]     = acc[nt][2] + b0;
                KVf[(rr + 8) * 136 + cc + 1] = acc[nt][3] + b1;
            }
        }
        __syncthreads();
        cpy68(W, gw_qkvo + 24576, 128, tid); // wo (overlaps o-compute)
        cp_commit();
        {   // o = attn @ V -> As fp16
            int rr = tid >> 2, d0 = (tid & 3) * 32;
            const float* vb = KVf + (rr & ~7) * 136;
            float a[8];
#pragma unroll
            for (int e = 0; e < 8; e++) a[e] = sc[rr * 8 + e];
            uint32_t* ar = As + rr * 68 + (d0 >> 1);
#pragma unroll
            for (int j = 0; j < 32; j += 4) {
                float4 o = make_float4(0.f, 0.f, 0.f, 0.f);
#pragma unroll
                for (int e = 0; e < 8; e++) {
                    float4 v = *(const float4*)&vb[e * 136 + d0 + j];
                    o.x += a[e] * v.x; o.y += a[e] * v.y;
                    o.z += a[e] * v.z; o.w += a[e] * v.w;
                }
                ar[(j >> 1)]     = pack2(o.x, o.y);
                ar[(j >> 1) + 1] = pack2(o.z, o.w);
            }
        }
        cp_wait<0>();
        __syncthreads();
        {   // wo gemm + residual -> g_xa
            float acc[8][4];
            zero_acc(&acc[0][0], 32);
            gemm_h<68, 68, 8>(acc, As, W, mbase, nbase, 64, q, t);
#pragma unroll
            for (int nt = 0; nt < 8; nt++) {
                int rr = mbase + q, cc = nbase + nt * 8 + 2 * t;
                float b0 = bo[cc], b1 = bo[cc + 1];
                size_t o0 = (rowbase + rr) * 128 + cc;
                size_t o1 = (rowbase + rr + 8) * 128 + cc;
                float2 x0 = *(const float2*)&x[o0];
                float2 x1 = *(const float2*)&x[o1];
                *(float2*)&g_xa[o0] = make_float2(x0.x + acc[nt][0] + b0,
                                                  x0.y + acc[nt][1] + b1);
                *(float2*)&g_xa[o1] = make_float2(x1.x + acc[nt][2] + b0,
                                                  x1.y + acc[nt][3] + b1);
            }
        }
        // publish
        __threadfence();
        __syncthreads();
        if (tid == 0) atomicExch(&g_done[tk], 1);
        return;
    }

    // =============== mega tile: (p0, g) ===============
    {
        const int i = tk - 2048;
        const int p0 = (i >> 6) * 64;
        const int g = i & 63;

        uint32_t* As = sm;                  // 64 x 68 (half)
        uint32_t* Zs = As + 4352;           // 64 x 36 (half)
        uint32_t* Ds = Zs + 2304;           // 64 x 36 (half)
        uint32_t* B0 = Ds + 2304;           // 8704
        uint32_t* B1 = B0 + 8704;           // 8704
        float* smu = (float*)(B1 + 8704);   // 64
        float* srs = smu + 64;              // 64
        float* pr  = srs + 64;              // 128

        // wait for the 64 producer tokens
        if (tid < 64) {
            while (atomicAdd(&g_done[p0 + tid], 0) == 0) __nanosleep(200);
            __threadfence();
        }
        __syncthreads();

        cpy68(B0, gw_enc + (size_t)g * 4096, 64, tid);   cp_commit();
        cpy36(B1, gw_pred + (size_t)g * 2048, 64, tid);  cp_commit();

        {   // As = fp16(x_attn), stats
            const int r = tid >> 2, h = tid & 3;
            const float* xr = g_xa + ((size_t)(p0 + r) * 64 + g) * 128 + h * 32;
            float xv[32];
            float s = 0.f, s2 = 0.f;
#pragma unroll
            for (int j = 0; j < 32; j += 4) {
                float4 v = *(const float4*)&xr[j];
                xv[j] = v.x; xv[j + 1] = v.y; xv[j + 2] = v.z; xv[j + 3] = v.w;
                s += v.x + v.y + v.z + v.w;
                s2 += v.x * v.x + v.y * v.y + v.z * v.z + v.w * v.w;
            }
            uint32_t* ar = As + r * 68 + h * 16;
#pragma unroll
            for (int j = 0; j < 32; j += 2)
                ar[j >> 1] = pack2(xv[j], xv[j + 1]);
            s  += __shfl_xor_sync(0xffffffffu, s, 1);
            s  += __shfl_xor_sync(0xffffffffu, s, 2);
            s2 += __shfl_xor_sync(0xffffffffu, s2, 1);
            s2 += __shfl_xor_sync(0xffffffffu, s2, 2);
            float mu = s * (1.f / 128.f);
            if (h == 0) {
                smu[r] = mu;
                srs[r] = rsqrtf(s2 * (1.f / 128.f) - mu * mu + 1e-5f);
            }
        }
        cp_wait<1>();     // enc ready
        __syncthreads();

        const int w = tid >> 5, lane = tid & 31, q = lane >> 2, t = lane & 3;
        const int mbase = (w & 3) * 16, wn = w >> 2;

        {   // enc GEMM
            float acc[4][4];
            zero_acc(&acc[0][0], 16);
            gemm_h<68, 68, 4>(acc, As, B0, mbase, wn * 32, 64, q, t);
            float sl = 0.f, sh = 0.f;
#pragma unroll
            for (int nt = 0; nt < 4; nt++) {
                int cc = wn * 32 + nt * 8 + 2 * t;
                int rlo = mbase + q, rhi = rlo + 8;
                float z0 = acc[nt][0] + encb[g * 64 + cc];
                float z1 = acc[nt][1] + encb[g * 64 + cc + 1];
                float z2 = acc[nt][2] + encb[g * 64 + cc];
                float z3 = acc[nt][3] + encb[g * 64 + cc + 1];
                size_t qlo = (size_t)(p0 + rlo) * 64 + g;
                size_t qhi = (size_t)(p0 + rhi) * 64 + g;
                *(float2*)&out[OFF_Z + qlo * 64 + cc] = make_float2(z0, z1);
                *(float2*)&out[OFF_Z + qhi * 64 + cc] = make_float2(z2, z3);
                float2 plo = *(const float2*)&zhp[qlo * 64 + cc];
                float2 phi = *(const float2*)&zhp[qhi * 64 + cc];
                float d0 = z0 - plo.x, d1 = z1 - plo.y;
                float d2 = z2 - phi.x, d3 = z3 - phi.y;
                int wi = cc >> 1;
                Zs[rlo * 36 + wi] = pack2(z0, z1);
                Zs[rhi * 36 + wi] = pack2(z2, z3);
                Ds[rlo * 36 + wi] = pack2(d0, d1);
                Ds[rhi * 36 + wi] = pack2(d2, d3);
                sl += d0 * d0 + d1 * d1;
                sh += d2 * d2 + d3 * d3;
            }
            sl += __shfl_xor_sync(0xffffffffu, sl, 1);
            sl += __shfl_xor_sync(0xffffffffu, sl, 2);
            sh += __shfl_xor_sync(0xffffffffu, sh, 1);
            sh += __shfl_xor_sync(0xffffffffu, sh, 2);
            if (t == 0) {
                pr[wn * 64 + mbase + q] = sl;
                pr[wn * 64 + mbase + q + 8] = sh;
            }
        }
        __syncthreads();
        if (tid < 64) {   // surprise + gate
            float sp = sqrtf(pr[tid] + pr[64 + tid]);
            size_t qq = (size_t)(p0 + tid) * 64 + g;
            out[OFF_S + qq] = sp;
            out[OFF_G + qq] = fminf(sp, 1.0f);
        }
        cpy68(B0, gw_up + (size_t)g * 32768, 128, tid);     cp_commit();   // up0
        cp_wait<1>();                                       // pred ready
        __syncthreads();
        {   // pred GEMM
            float acc[4][4];
            zero_acc(&acc[0][0], 16);
            gemm_h<36, 36, 4>(acc, Zs, B1, mbase, wn * 32, 32, q, t);
#pragma unroll
            for (int nt = 0; nt < 4; nt++) {
                int cc = wn * 32 + nt * 8 + 2 * t;
                size_t qlo = (size_t)(p0 + mbase + q) * 64 + g;
                size_t qhi = (size_t)(p0 + mbase + q + 8) * 64 + g;
                float b0 = predb[g * 64 + cc], b1 = predb[g * 64 + cc + 1];
                *(float2*)&out[OFF_ZH + qlo * 64 + cc] =
                    make_float2(acc[nt][0] + b0, acc[nt][1] + b1);
                *(float2*)&out[OFF_ZH + qhi * 64 + cc] =
                    make_float2(acc[nt][2] + b0, acc[nt][3] + b1);
            }
        }
        __syncthreads();
        cpy36(B1, gw_gain + (size_t)g * 4096, 128, tid);    cp_commit();   // gain
        cp_wait<0>();
        __syncthreads();
        {   // gain GEMM + GLN epilogue -> As := fp16(hh)
            float acc[8][4];
            zero_acc(&acc[0][0], 32);
            gemm_h<36, 36, 8>(acc, Ds, B1, mbase, wn * 64, 32, q, t);
            int rlo = mbase + q, rhi = rlo + 8;
            float mlo = smu[rlo], rslo = srs[rlo];
            float mhi = smu[rhi], rshi = srs[rhi];
#pragma unroll
            for (int nt = 0; nt < 8; nt++) {
                int cc = wn * 64 + nt * 8 + 2 * t, wi = cc >> 1;
                float lg0 = lng[(size_t)g * 128 + cc], lb0 = lnb[(size_t)g * 128 + cc];
                float lg1 = lng[(size_t)g * 128 + cc + 1], lb1 = lnb[(size_t)g * 128 + cc + 1];
                float gb0 = gainb[(size_t)g * 128 + cc], gb1 = gainb[(size_t)g * 128 + cc + 1];
                float2 xlo = unp2(As[rlo * 68 + wi]);
                float2 xhi = unp2(As[rhi * 68 + wi]);
                float h00 = ((xlo.x - mlo) * rslo * lg0 + lb0)
                            * (1.0f + 0.1f * tanhf(acc[nt][0] + gb0));
                float h01 = ((xlo.y - mlo) * rslo * lg1 + lb1)
                            * (1.0f + 0.1f * tanhf(acc[nt][1] + gb1));
                float h10 = ((xhi.x - mhi) * rshi * lg0 + lb0)
                            * (1.0f + 0.1f * tanhf(acc[nt][2] + gb0));
                float h11 = ((xhi.y - mhi) * rshi * lg1 + lb1)
                            * (1.0f + 0.1f * tanhf(acc[nt][3] + gb1));
                As[rlo * 68 + wi] = pack2(h00, h01);
                As[rhi * 68 + wi] = pack2(h10, h11);
            }
        }
        __syncthreads();
        cpy68(B1, gw_down + (size_t)g * 32768, 128, tid);   cp_commit();   // down0

        uint32_t* Us = Zs;
        float oacc[8][4];
        zero_acc(&oacc[0][0], 32);
        for (int ch = 0; ch < 4; ch++) {
            float uacc[8][4];
            zero_acc(&uacc[0][0], 32);
            gemm_h<68, 68, 8>(uacc, As, B0, mbase, wn * 64, 64, q, t);
#pragma unroll
            for (int nt = 0; nt < 8; nt++) {
                int cc = wn * 64 + nt * 8 + 2 * t, wi = cc >> 1;
                int rlo = mbase + q, rhi = rlo + 8;
                float b0 = upb[(size_t)g * 512 + ch * 128 + cc];
                float b1 = upb[(size_t)g * 512 + ch * 128 + cc + 1];
                float u00 = uacc[nt][0] + b0, u01 = uacc[nt][1] + b1;
                float u10 = uacc[nt][2] + b0, u11 = uacc[nt][3] + b1;
                u00 = 0.5f * u00 * (1.0f + erff(u00 * 0.70710678118654752f));
                u01 = 0.5f * u01 * (1.0f + erff(u01 * 0.70710678118654752f));
                u10 = 0.5f * u10 * (1.0f + erff(u10 * 0.70710678118654752f));
                u11 = 0.5f * u11 * (1.0f + erff(u11 * 0.70710678118654752f));
                Us[rlo * 68 + wi] = pack2(u00, u01);
                Us[rhi * 68 + wi] = pack2(u10, u11);
            }
            __syncthreads();
            if (ch < 3) {
                cpy68(B0, gw_up + (size_t)g * 32768 + (ch + 1) * 8192, 128, tid);
                cp_commit();
                cp_wait<1>();
            } else {
                cp_wait<0>();
            }
            __syncthreads();
            gemm_h<68, 68, 8>(oacc, Us, B1, mbase, wn * 64, 64, q, t);
            if (ch < 3) {
                __syncthreads();
                cpy68(B1, gw_down + (size_t)g * 32768 + (ch + 1) * 8192, 128, tid);
                cp_commit();
                cp_wait<1>();
                __syncthreads();
            }
        }
        __syncthreads();
        {   // MLP epilogue -> gmem x_out AND As := fp16(x_out)
#pragma unroll
            for (int nt = 0; nt < 8; nt++) {
                int cc = wn * 64 + nt * 8 + 2 * t, wi = cc >> 1;
                int rlo = mbase + q, rhi = rlo + 8;
                float b0 = dwb[(size_t)g * 128 + cc], b1 = dwb[(size_t)g * 128 + cc + 1];
                size_t o0 = ((size_t)(p0 + rlo) * 64 + g) * 128 + cc;
                size_t o1 = ((size_t)(p0 + rhi) * 64 + g) * 128 + cc;
                float2 x0 = *(const float2*)&g_xa[o0];
                float2 x1 = *(const float2*)&g_xa[o1];
                float v00 = x0.x + oacc[nt][0] + b0, v01 = x0.y + oacc[nt][1] + b1;
                float v10 = x1.x + oacc[nt][2] + b0, v11 = x1.y + oacc[nt][3] + b1;
                *(float2*)&out[OFF_XOUT + o0] = make_float2(v00, v01);
                *(float2*)&out[OFF_XOUT + o1] = make_float2(v10, v11);
                As[rlo * 68 + wi] = pack2(v00, v01);
                As[rhi * 68 + wi] = pack2(v10, v11);
            }
        }
        __syncthreads();
        cpy68(B0, gw_post + (size_t)g * 32768, 128, tid);         cp_commit();
        cpy68(B1, gw_post + (size_t)g * 32768 + 8192, 128, tid);  cp_commit();

        if (tid < 64) {   // w_nov
            const float* wl = gw_plast + g * 128;
            float s = 0.f;
            for (int kw = 0; kw < 64; kw++) {
                float2 xv = unp2(As[tid * 68 + kw]);
                s += xv.x * wl[2 * kw] + xv.y * wl[2 * kw + 1];
            }
            s += pb[(size_t)g * 513 + 512];
            out[OFF_WN + (size_t)(p0 + tid) * 64 + g] = 1.0f / (1.0f + expf(-s));
        }

        for (int ch = 0; ch < 4; ch++) {
            if (ch < 3) cp_wait<1>(); else cp_wait<0>();
            __syncthreads();
            uint32_t* Bs = (ch & 1) ? B1 : B0;
            float acc[8][4];
            zero_acc(&acc[0][0], 32);
            gemm_h<68, 68, 8>(acc, As, Bs, mbase, wn * 64, 64, q, t);
#pragma unroll
            for (int nt = 0; nt < 8; nt++) {
                int cc = wn * 64 + nt * 8 + 2 * t;
                float b0 = pb[(size_t)g * 513 + ch * 128 + cc];
                float b1 = pb[(size_t)g * 513 + ch * 128 + cc + 1];
                acc[nt][0] += b0; acc[nt][1] += b1;
                acc[nt][2] += b0; acc[nt][3] += b1;
            }
            if (ch == 1 || ch == 3) {
                size_t off = (ch == 1) ? OFF_VP : OFF_VC;
#pragma unroll
                for (int nt = 0; nt < 8; nt++) {
                    int rr = mbase + q, cc = wn * 64 + nt * 8 + 2 * t;
                    size_t o0 = off + ((size_t)(p0 + rr) * 64 + g) * 128 + cc;
                    size_t o1 = off + ((size_t)(p0 + rr + 8) * 64 + g) * 128 + cc;
                    *(float2*)&out[o0] = make_float2(acc[nt][0], acc[nt][1]);
                    *(float2*)&out[o1] = make_float2(acc[nt][2], acc[nt][3]);
                }
            } else {
                float sl = 0.f, sh = 0.f;
#pragma unroll
                for (int nt = 0; nt < 8; nt++) {
                    sl += acc[nt][0] * acc[nt][0] + acc[nt][1] * acc[nt][1];
                    sh += acc[nt][2] * acc[nt][2] + acc[nt][3] * acc[nt][3];
                }
                sl += __shfl_xor_sync(0xffffffffu, sl, 1);
                sl += __shfl_xor_sync(0xffffffffu, sl, 2);
                sh += __shfl_xor_sync(0xffffffffu, sh, 1);
                sh += __shfl_xor_sync(0xffffffffu, sh, 2);
                if (t == 0) {
                    pr[wn * 64 + mbase + q] = sl;
                    pr[wn * 64 + mbase + q + 8] = sh;
                }
                __syncthreads();
                size_t off = (ch == 0) ? OFF_KC : OFF_QN;
#pragma unroll
                for (int nt = 0; nt < 8; nt++) {
                    int rr = mbase + q, cc = wn * 64 + nt * 8 + 2 * t;
                    float i0 = 1.0f / fmaxf(sqrtf(pr[rr] + pr[64 + rr]), 1e-6f);
                    float i1 = 1.0f / fmaxf(sqrtf(pr[rr + 8] + pr[64 + rr + 8]), 1e-6f);
                    size_t o0 = off + ((size_t)(p0 + rr) * 64 + g) * 128 + cc;
                    size_t o1 = off + ((size_t)(p0 + rr + 8) * 64 + g) * 128 + cc;
                    *(float2*)&out[o0] = make_float2(acc[nt][0] * i0, acc[nt][1] * i0);
                    *(float2*)&out[o1] = make_float2(acc[nt][2] * i1, acc[nt][3] * i1);
                }
            }
            if (ch < 2) {
                __syncthreads();
                cpy68((ch & 1) ? B1 : B0,
                      gw_post + (size_t)g * 32768 + (ch + 2) * 8192, 128, tid);
                cp_commit();
            }
        }
    }
}

// ===========================================================================
extern "C" void kernel_launch(void* const* d_in, const int* in_sizes, int n_in,
                              void* d_out, int out_size) {
    const float* x_col  = (const float*)d_in[0];
    const float* zhp    = (const float*)d_in[1];
    const float* ln_g   = (const float*)d_in[2];
    const float* ln_b   = (const float*)d_in[3];
    const float* up_w   = (const float*)d_in[4];
    const float* up_b   = (const float*)d_in[5];
    const float* down_w = (const float*)d_in[6];
    const float* down_b = (const float*)d_in[7];
    const float* lat_g  = (const float*)d_in[8];
    const float* lat_b  = (const float*)d_in[9];
    const float* wq     = (const float*)d_in[10];
    const float* bq     = (const float*)d_in[11];
    const float* wk     = (const float*)d_in[12];
    const float* bk     = (const float*)d_in[13];
    const float* wv     = (const float*)d_in[14];
    const float* bv     = (const float*)d_in[15];
    const float* wo     = (const float*)d_in[16];
    const float* bo     = (const float*)d_in[17];
    const float* post_w = (const float*)d_in[18];
    const float* post_b = (const float*)d_in[19];
    const float* enc_w  = (const float*)d_in[20];
    const float* enc_b  = (const float*)d_in[21];
    const float* pred_w = (const float*)d_in[22];
    const float* pred_b = (const float*)d_in[23];
    const float* gain_w = (const float*)d_in[24];
    const float* gain_b = (const float*)d_in[25];
    float* out = (float*)d_out;

    const int SM_ALL = 26880 * 4;   // 107520 (2 CTAs/SM)

    cudaFuncSetAttribute(k_all, cudaFuncAttributeMaxDynamicSharedMemorySize, SM_ALL);

    uint32_t* d_enc;  cudaGetSymbolAddress((void**)&d_enc,  gw_enc);
    uint32_t* d_pred; cudaGetSymbolAddress((void**)&d_pred, gw_pred);
    uint32_t* d_gain; cudaGetSymbolAddress((void**)&d_gain, gw_gain);
    uint32_t* d_up;   cudaGetSymbolAddress((void**)&d_up,   gw_up);
    uint32_t* d_down; cudaGetSymbolAddress((void**)&d_down, gw_down);
    uint32_t* d_post; cudaGetSymbolAddress((void**)&d_post, gw_post);

    k_reset<<<8, 256>>>();
    k_tcvt_qkvo2<<<dim3(4, 4, 4), 256>>>(wq, wk, wv, wo);
    k_tcvt2<<<dim3(4, 2, 64), 256>>>(enc_w, d_enc, 8192, 64, 4096,
                                     6, 0, 7, 0, 63, 64, 127);
    k_tcvt2<<<dim3(2, 2, 64), 256>>>(pred_w, d_pred, 4096, 64, 2048,
                                     6, 0, 6, 0, 63, 32, 63);
    k_tcvt2<<<dim3(2, 4, 64), 256>>>(gain_w, d_gain, 8192, 128, 4096,
                                     7, 0, 6, 0, 127, 32, 63);
    k_tcvt2<<<dim3(4, 16, 64), 256>>>(up_w, d_up, 65536, 512, 32768,
                                      7, 8192, 7, 0, 127, 64, 127);
    k_tcvt2<<<dim3(16, 4, 64), 256>>>(down_w, d_down, 65536, 128, 32768,
                                      7, 0, 7, 8192, 127, 64, 127);
    k_tcvt2<<<dim3(4, 16, 64), 256>>>(post_w, d_post, 65664, 513, 32768,
                                      7, 8192, 7, 0, 127, 64, 127);
    k_plast<<<32, 256>>>(post_w);

    k_all<<<4096, 256, SM_ALL>>>(x_col, lat_g, lat_b, bq, bk, bv, bo,
                                 zhp, ln_g, ln_b, enc_b, pred_b, gain_b,
                                 up_b, down_b, post_b, out);
}